// round 1
// baseline (speedup 1.0000x reference)
#include <cuda_runtime.h>
#include <cuda_bf16.h>
#include <math.h>

// ---------------- problem constants ----------------
#define L_  6
#define B_  2
#define T_  1024
#define C_  768
#define H_  12
#define D_  64
#define F_  3072
#define V_  50257
#define M_  (B_ * T_)          // 2048 rows
#define EPS_ 1e-5f

// ---------------- scratch (device globals, no runtime alloc) ----------------
__device__ float g_x  [M_ * C_];        // residual stream
__device__ float g_ln [M_ * C_];        // layernorm output
__device__ float g_qkv[M_ * 3 * C_];    // qkv projection
__device__ float g_att[M_ * C_];        // attention output
__device__ float g_mid[M_ * F_];        // mlp hidden

// ---------------- embedding ----------------
__global__ void embed_kernel(const int* __restrict__ idx,
                             const float* __restrict__ wte,
                             const float* __restrict__ pte,
                             float* __restrict__ x) {
    int r = blockIdx.x;                 // 0..M_-1  (b*T + t)
    int t = r % T_;
    int tok = idx[r];
    const float* wrow = wte + (size_t)tok * C_;
    const float* prow = pte + (size_t)t * C_;
    float* xr = x + (size_t)r * C_;
    for (int c = threadIdx.x; c < C_; c += blockDim.x)
        xr[c] = wrow[c] + prow[c];
}

// ---------------- layernorm (one block per row, C=768) ----------------
__global__ void layernorm_kernel(const float* __restrict__ x,
                                 const float* __restrict__ sc,
                                 const float* __restrict__ bi,
                                 float* __restrict__ y) {
    __shared__ float sh1[256];
    __shared__ float sh2[256];
    int r = blockIdx.x;
    int tid = threadIdx.x;
    const float* xr = x + (size_t)r * C_;
    float v0 = xr[tid], v1 = xr[tid + 256], v2 = xr[tid + 512];
    float s  = v0 + v1 + v2;
    float ss = v0 * v0 + v1 * v1 + v2 * v2;
    sh1[tid] = s; sh2[tid] = ss;
    __syncthreads();
    for (int off = 128; off > 0; off >>= 1) {
        if (tid < off) { sh1[tid] += sh1[tid + off]; sh2[tid] += sh2[tid + off]; }
        __syncthreads();
    }
    float mu  = sh1[0] * (1.0f / C_);
    float var = sh2[0] * (1.0f / C_) - mu * mu;
    float rstd = rsqrtf(var + EPS_);
    float* yr = y + (size_t)r * C_;
    yr[tid]        = (v0 - mu) * rstd * sc[tid]        + bi[tid];
    yr[tid + 256]  = (v1 - mu) * rstd * sc[tid + 256]  + bi[tid + 256];
    yr[tid + 512]  = (v2 - mu) * rstd * sc[tid + 512]  + bi[tid + 512];
}

// ---------------- flash-style attention: one warp per query row ----------------
__global__ void attn_kernel(const float* __restrict__ qkv,
                            float* __restrict__ out) {
    int lane = threadIdx.x;                 // 0..31
    int q = blockIdx.x * blockDim.y + threadIdx.y;   // 0..T-1
    int bh = blockIdx.y;
    int b = bh / H_, h = bh % H_;

    const float* base = qkv + (size_t)b * T_ * 3 * C_;
    const float* qp = base + (size_t)q * 3 * C_ + h * D_;
    float q0 = qp[lane]      * 0.125f;      // 1/sqrt(64)
    float q1 = qp[lane + 32] * 0.125f;

    float m = -3.0e38f, l = 0.0f, a0 = 0.0f, a1 = 0.0f;
    for (int j = 0; j <= q; j++) {
        const float* kp = base + (size_t)j * 3 * C_ + C_ + h * D_;
        float s = q0 * kp[lane] + q1 * kp[lane + 32];
        #pragma unroll
        for (int off = 16; off > 0; off >>= 1)
            s += __shfl_xor_sync(0xffffffff, s, off);
        float mn   = fmaxf(m, s);
        float corr = __expf(m - mn);
        float p    = __expf(s - mn);
        const float* vp = base + (size_t)j * 3 * C_ + 2 * C_ + h * D_;
        l  = l  * corr + p;
        a0 = a0 * corr + p * vp[lane];
        a1 = a1 * corr + p * vp[lane + 32];
        m = mn;
    }
    float inv = 1.0f / l;
    float* orow = out + (size_t)(b * T_ + q) * C_ + h * D_;
    orow[lane]      = a0 * inv;
    orow[lane + 32] = a1 * inv;
}

// ---------------- generic SGEMM: C = A[MxK] @ B[KxN] (+bias)(+gelu)(+res) ----------------
__device__ __forceinline__ float gelu_exact(float v) {
    return 0.5f * v * (1.0f + erff(v * 0.70710678118654752f));
}

template<int HAS_BIAS, int DO_GELU, int DO_RES>
__global__ __launch_bounds__(256) void sgemm_kernel(
        const float* __restrict__ A, const float* __restrict__ Bm,
        const float* __restrict__ bias, const float* __restrict__ res,
        float* __restrict__ Cm, int M, int N, int K) {
    __shared__ float As[8][128];
    __shared__ float Bs[8][128];

    int tid = threadIdx.x;
    int tx = tid & 15, ty = tid >> 4;
    int m0 = blockIdx.y * 128, n0 = blockIdx.x * 128;

    float acc[8][8];
    #pragma unroll
    for (int i = 0; i < 8; i++)
        #pragma unroll
        for (int j = 0; j < 8; j++) acc[i][j] = 0.0f;

    int arow = tid >> 1;            // 0..127
    int acol = (tid & 1) * 4;       // 0 or 4

    for (int k0 = 0; k0 < K; k0 += 8) {
        // A tile: 128x8, vectorized load, stored transposed
        float4 av = *(const float4*)(A + (size_t)(m0 + arow) * K + k0 + acol);
        As[acol + 0][arow] = av.x;
        As[acol + 1][arow] = av.y;
        As[acol + 2][arow] = av.z;
        As[acol + 3][arow] = av.w;
        // B tile: 8x128, scalar coalesced with N guard
        #pragma unroll
        for (int i = 0; i < 4; i++) {
            int e = tid + 256 * i;
            int br = e >> 7, bc = e & 127;
            int col = n0 + bc;
            Bs[br][bc] = (col < N) ? Bm[(size_t)(k0 + br) * N + col] : 0.0f;
        }
        __syncthreads();
        #pragma unroll
        for (int k = 0; k < 8; k++) {
            float a[8], bb[8];
            #pragma unroll
            for (int i = 0; i < 8; i++) a[i]  = As[k][ty * 8 + i];
            #pragma unroll
            for (int j = 0; j < 8; j++) bb[j] = Bs[k][tx * 8 + j];
            #pragma unroll
            for (int i = 0; i < 8; i++)
                #pragma unroll
                for (int j = 0; j < 8; j++)
                    acc[i][j] = fmaf(a[i], bb[j], acc[i][j]);
        }
        __syncthreads();
    }

    #pragma unroll
    for (int i = 0; i < 8; i++) {
        int row = m0 + ty * 8 + i;
        #pragma unroll
        for (int j = 0; j < 8; j++) {
            int col = n0 + tx * 8 + j;
            if (col < N) {
                float v = acc[i][j];
                if (HAS_BIAS) v += bias[col];
                if (DO_GELU)  v = gelu_exact(v);
                if (DO_RES)   v += res[(size_t)row * N + col];
                Cm[(size_t)row * N + col] = v;
            }
        }
    }
}

// ---------------- launch ----------------
extern "C" void kernel_launch(void* const* d_in, const int* in_sizes, int n_in,
                              void* d_out, int out_size) {
    const int*   idx    = (const int*)  d_in[0];
    const float* wte    = (const float*)d_in[1];
    const float* pte    = (const float*)d_in[2];
    const float* ln1_s  = (const float*)d_in[3];
    const float* ln1_b  = (const float*)d_in[4];
    const float* qkv_w  = (const float*)d_in[5];
    const float* qkv_b  = (const float*)d_in[6];
    const float* proj_w = (const float*)d_in[7];
    const float* proj_b = (const float*)d_in[8];
    const float* ln2_s  = (const float*)d_in[9];
    const float* ln2_b  = (const float*)d_in[10];
    const float* w1     = (const float*)d_in[11];
    const float* b1     = (const float*)d_in[12];
    const float* w2     = (const float*)d_in[13];
    const float* b2     = (const float*)d_in[14];
    const float* lnf_s  = (const float*)d_in[15];
    const float* lnf_b  = (const float*)d_in[16];
    const float* head_w = (const float*)d_in[17];
    float* out = (float*)d_out;

    float *px, *pln, *pqkv, *patt, *pmid;
    cudaGetSymbolAddress((void**)&px,   g_x);
    cudaGetSymbolAddress((void**)&pln,  g_ln);
    cudaGetSymbolAddress((void**)&pqkv, g_qkv);
    cudaGetSymbolAddress((void**)&patt, g_att);
    cudaGetSymbolAddress((void**)&pmid, g_mid);

    embed_kernel<<<M_, 256>>>(idx, wte, pte, px);

    for (int l = 0; l < L_; l++) {
        const float* l1s = ln1_s  + (size_t)l * C_;
        const float* l1b = ln1_b  + (size_t)l * C_;
        const float* qw  = qkv_w  + (size_t)l * C_ * 3 * C_;
        const float* qb  = qkv_b  + (size_t)l * 3 * C_;
        const float* pw  = proj_w + (size_t)l * C_ * C_;
        const float* pb  = proj_b + (size_t)l * C_;
        const float* l2s = ln2_s  + (size_t)l * C_;
        const float* l2b = ln2_b  + (size_t)l * C_;
        const float* m1w = w1     + (size_t)l * C_ * F_;
        const float* m1b = b1     + (size_t)l * F_;
        const float* m2w = w2     + (size_t)l * F_ * C_;
        const float* m2b = b2     + (size_t)l * C_;

        layernorm_kernel<<<M_, 256>>>(px, l1s, l1b, pln);

        // qkv = ln @ qkv_w + qkv_b   [2048 x 2304]
        sgemm_kernel<1,0,0><<<dim3(3 * C_ / 128, M_ / 128), 256>>>(
            pln, qw, qb, nullptr, pqkv, M_, 3 * C_, C_);

        // attention
        attn_kernel<<<dim3(T_ / 4, B_ * H_), dim3(32, 4)>>>(pqkv, patt);

        // x = x + att @ proj_w + proj_b   [2048 x 768]
        sgemm_kernel<1,0,1><<<dim3(C_ / 128, M_ / 128), 256>>>(
            patt, pw, pb, px, px, M_, C_, C_);

        layernorm_kernel<<<M_, 256>>>(px, l2s, l2b, pln);

        // mid = gelu(ln2 @ w1 + b1)   [2048 x 3072]
        sgemm_kernel<1,1,0><<<dim3(F_ / 128, M_ / 128), 256>>>(
            pln, m1w, m1b, nullptr, pmid, M_, F_, C_);

        // x = x + mid @ w2 + b2   [2048 x 768]
        sgemm_kernel<1,0,1><<<dim3(C_ / 128, M_ / 128), 256>>>(
            pmid, m2w, m2b, px, px, M_, C_, F_);
    }

    layernorm_kernel<<<M_, 256>>>(px, lnf_s, lnf_b, pln);

    // logits = lnf @ head_w   [2048 x 50257]
    sgemm_kernel<0,0,0><<<dim3((V_ + 127) / 128, M_ / 128), 256>>>(
        pln, head_w, nullptr, nullptr, out, M_, V_, C_);
}

// round 3
// speedup vs baseline: 1.8988x; 1.8988x over previous
#include <cuda_runtime.h>
#include <cuda_bf16.h>
#include <math.h>
#include <stdint.h>

// ---------------- problem constants ----------------
#define L_  6
#define B_  2
#define T_  1024
#define C_  768
#define H_  12
#define D_  64
#define F_  3072
#define V_  50257
#define M_  (B_ * T_)          // 2048 rows
#define EPS_ 1e-5f

// ---------------- scratch (device globals, no runtime alloc) ----------------
__device__ float g_x  [M_ * C_];
__device__ float g_ln [M_ * C_];
__device__ float g_qkv[M_ * 3 * C_];
__device__ float g_att[M_ * C_];
__device__ float g_mid[M_ * F_];

// ---------------- embedding ----------------
__global__ void embed_kernel(const int* __restrict__ idx,
                             const float* __restrict__ wte,
                             const float* __restrict__ pte,
                             float* __restrict__ x) {
    int r = blockIdx.x;
    int t = r % T_;
    int tok = idx[r];
    const float* wrow = wte + (size_t)tok * C_;
    const float* prow = pte + (size_t)t * C_;
    float* xr = x + (size_t)r * C_;
    for (int c = threadIdx.x; c < C_; c += blockDim.x)
        xr[c] = wrow[c] + prow[c];
}

// ---------------- layernorm ----------------
__global__ void layernorm_kernel(const float* __restrict__ x,
                                 const float* __restrict__ sc,
                                 const float* __restrict__ bi,
                                 float* __restrict__ y) {
    __shared__ float sh1[256];
    __shared__ float sh2[256];
    int r = blockIdx.x;
    int tid = threadIdx.x;
    const float* xr = x + (size_t)r * C_;
    float v0 = xr[tid], v1 = xr[tid + 256], v2 = xr[tid + 512];
    float s  = v0 + v1 + v2;
    float ss = v0 * v0 + v1 * v1 + v2 * v2;
    sh1[tid] = s; sh2[tid] = ss;
    __syncthreads();
    for (int off = 128; off > 0; off >>= 1) {
        if (tid < off) { sh1[tid] += sh1[tid + off]; sh2[tid] += sh2[tid + off]; }
        __syncthreads();
    }
    float mu  = sh1[0] * (1.0f / C_);
    float var = sh2[0] * (1.0f / C_) - mu * mu;
    float rstd = rsqrtf(var + EPS_);
    float* yr = y + (size_t)r * C_;
    yr[tid]        = (v0 - mu) * rstd * sc[tid]        + bi[tid];
    yr[tid + 256]  = (v1 - mu) * rstd * sc[tid + 256]  + bi[tid + 256];
    yr[tid + 512]  = (v2 - mu) * rstd * sc[tid + 512]  + bi[tid + 512];
}

// ---------------- flash-style attention: one warp per query row ----------------
__global__ void attn_kernel(const float* __restrict__ qkv,
                            float* __restrict__ out) {
    int lane = threadIdx.x;
    int q = blockIdx.x * blockDim.y + threadIdx.y;
    int bh = blockIdx.y;
    int b = bh / H_, h = bh % H_;

    const float* base = qkv + (size_t)b * T_ * 3 * C_;
    const float* qp = base + (size_t)q * 3 * C_ + h * D_;
    float q0 = qp[lane]      * 0.125f;
    float q1 = qp[lane + 32] * 0.125f;

    float m = -3.0e38f, l = 0.0f, a0 = 0.0f, a1 = 0.0f;
    for (int j = 0; j <= q; j++) {
        const float* kp = base + (size_t)j * 3 * C_ + C_ + h * D_;
        float s = q0 * kp[lane] + q1 * kp[lane + 32];
        #pragma unroll
        for (int off = 16; off > 0; off >>= 1)
            s += __shfl_xor_sync(0xffffffff, s, off);
        float mn   = fmaxf(m, s);
        float corr = __expf(m - mn);
        float p    = __expf(s - mn);
        const float* vp = base + (size_t)j * 3 * C_ + 2 * C_ + h * D_;
        l  = l  * corr + p;
        a0 = a0 * corr + p * vp[lane];
        a1 = a1 * corr + p * vp[lane + 32];
        m = mn;
    }
    float inv = 1.0f / l;
    float* orow = out + (size_t)(b * T_ + q) * C_ + h * D_;
    orow[lane]      = a0 * inv;
    orow[lane + 32] = a1 * inv;
}

// ================= split-bf16 mma.sync GEMM =================
// C = A @ B via Ahi*Bhi + Ahi*Blo + Alo*Bhi, fp32 accumulate.
// Tile 128x128, BK=64, 256 threads, double-buffered smem (128KB).
// smem per buffer (64KB): Ahi[128][64]bf16 @0, Alo @16384, Bhi[64][128]bf16 @32768, Blo @49152

__device__ __forceinline__ uint32_t smem_u32(const void* p) {
    uint32_t a;
    asm("{ .reg .u64 t; cvta.to.shared.u64 t, %1; cvt.u32.u64 %0, t; }" : "=r"(a) : "l"(p));
    return a;
}

__device__ __forceinline__ void ldsm_x4(uint32_t* r, uint32_t a) {
    asm volatile("ldmatrix.sync.aligned.m8n8.x4.shared.b16 {%0,%1,%2,%3}, [%4];"
        : "=r"(r[0]), "=r"(r[1]), "=r"(r[2]), "=r"(r[3]) : "r"(a));
}
__device__ __forceinline__ void ldsm_x2t(uint32_t* r, uint32_t a) {
    asm volatile("ldmatrix.sync.aligned.m8n8.x2.trans.shared.b16 {%0,%1}, [%2];"
        : "=r"(r[0]), "=r"(r[1]) : "r"(a));
}
__device__ __forceinline__ void mma16816(float* d, const uint32_t* a, const uint32_t* b) {
    asm volatile("mma.sync.aligned.m16n8k16.row.col.f32.bf16.bf16.f32 "
        "{%0,%1,%2,%3}, {%4,%5,%6,%7}, {%8,%9}, {%0,%1,%2,%3};"
        : "+f"(d[0]), "+f"(d[1]), "+f"(d[2]), "+f"(d[3])
        : "r"(a[0]), "r"(a[1]), "r"(a[2]), "r"(a[3]), "r"(b[0]), "r"(b[1]));
}

__device__ __forceinline__ void split2(float x, float y, uint32_t& h, uint32_t& l) {
    __nv_bfloat16 hx = __float2bfloat16(x), hy = __float2bfloat16(y);
    __nv_bfloat16 lx = __float2bfloat16(x - __bfloat162float(hx));
    __nv_bfloat16 ly = __float2bfloat16(y - __bfloat162float(hy));
    h = (uint32_t)__bfloat16_as_ushort(hx) | ((uint32_t)__bfloat16_as_ushort(hy) << 16);
    l = (uint32_t)__bfloat16_as_ushort(lx) | ((uint32_t)__bfloat16_as_ushort(ly) << 16);
}

__device__ __forceinline__ float gelu_exact(float v) {
    return 0.5f * v * (1.0f + erff(v * 0.70710678118654752f));
}

template<int HAS_BIAS, int DO_GELU, int DO_RES>
__global__ __launch_bounds__(256, 1) void tc_gemm(
        const float* __restrict__ A, const float* __restrict__ Bm,
        const float* __restrict__ bias, const float* __restrict__ res,
        float* __restrict__ Cm, int M, int N, int K) {
    extern __shared__ __align__(1024) char dsm[];
    uint32_t sb = smem_u32(dsm);
    const int tid = threadIdx.x, lane = tid & 31, wid = tid >> 5;
    const int wm = wid >> 2, wn = wid & 3;             // 2 x 4 warp grid
    const int m0 = blockIdx.x * 128, n0 = blockIdx.y * 128;
    const int niter = K >> 6;
    const bool vecb = ((N & 3) == 0) && (n0 + 128 <= N);

    float acc[4][4][4];
    #pragma unroll
    for (int a = 0; a < 4; a++)
        #pragma unroll
        for (int b = 0; b < 4; b++)
            #pragma unroll
            for (int c = 0; c < 4; c++) acc[a][b][c] = 0.0f;

    float4 stA[8], stB[8];

    auto LOADG = [&](int k0) {
        #pragma unroll
        for (int i = 0; i < 8; i++) {
            int e = tid + 256 * i;
            int r = e >> 4, kq = e & 15;
            stA[i] = *(const float4*)(A + (size_t)(m0 + r) * K + k0 + kq * 4);
        }
        #pragma unroll
        for (int i = 0; i < 8; i++) {
            int e = tid + 256 * i;
            int kr = e >> 5, nq = e & 31;
            if (vecb) {
                stB[i] = *(const float4*)(Bm + (size_t)(k0 + kr) * N + n0 + nq * 4);
            } else {
                float v[4];
                #pragma unroll
                for (int j = 0; j < 4; j++) {
                    int col = n0 + nq * 4 + j;
                    v[j] = (col < N) ? Bm[(size_t)(k0 + kr) * N + col] : 0.0f;
                }
                stB[i] = make_float4(v[0], v[1], v[2], v[3]);
            }
        }
    };

    auto STS = [&](int bufoff) {
        #pragma unroll
        for (int i = 0; i < 8; i++) {
            int e = tid + 256 * i;
            int r = e >> 4, kq = e & 15;
            uint32_t off = (uint32_t)(r * 128 + (((kq >> 1) ^ (r & 7)) << 4) + (kq & 1) * 8);
            uint32_t h0, l0, h1, l1;
            split2(stA[i].x, stA[i].y, h0, l0);
            split2(stA[i].z, stA[i].w, h1, l1);
            *(uint2*)(dsm + bufoff + off)         = make_uint2(h0, h1);
            *(uint2*)(dsm + bufoff + 16384 + off) = make_uint2(l0, l1);
        }
        #pragma unroll
        for (int i = 0; i < 8; i++) {
            int e = tid + 256 * i;
            int kr = e >> 5, nq = e & 31;
            uint32_t off = (uint32_t)(kr * 256 + (((nq >> 1) ^ (kr & 7)) << 4) + (nq & 1) * 8);
            uint32_t h0, l0, h1, l1;
            split2(stB[i].x, stB[i].y, h0, l0);
            split2(stB[i].z, stB[i].w, h1, l1);
            *(uint2*)(dsm + bufoff + 32768 + off) = make_uint2(h0, h1);
            *(uint2*)(dsm + bufoff + 49152 + off) = make_uint2(l0, l1);
        }
    };

    auto COMPUTE = [&](uint32_t aBase, uint32_t bBase) {
        #pragma unroll
        for (int ks = 0; ks < 4; ks++) {
            uint32_t ah[4][4], alr[4][4];
            #pragma unroll
            for (int mt = 0; mt < 4; mt++) {
                int r = wm * 64 + mt * 16 + (lane & 15);
                int c = ks * 2 + (lane >> 4);
                uint32_t off = (uint32_t)(r * 128 + ((c ^ (r & 7)) << 4));
                ldsm_x4(ah[mt],  aBase + off);
                ldsm_x4(alr[mt], aBase + 16384 + off);
            }
            uint32_t bh[4][2], blr[4][2];
            #pragma unroll
            for (int nt = 0; nt < 4; nt++) {
                int kt = ks * 16 + (lane & 15);
                int c = wn * 4 + nt;
                uint32_t off = (uint32_t)(kt * 256 + ((c ^ (kt & 7)) << 4));
                ldsm_x2t(bh[nt],  bBase + off);
                ldsm_x2t(blr[nt], bBase + 16384 + off);
            }
            #pragma unroll
            for (int mt = 0; mt < 4; mt++)
                #pragma unroll
                for (int nt = 0; nt < 4; nt++) {
                    mma16816(acc[mt][nt], ah[mt],  bh[nt]);
                    mma16816(acc[mt][nt], ah[mt],  blr[nt]);
                    mma16816(acc[mt][nt], alr[mt], bh[nt]);
                }
        }
    };

    LOADG(0);
    STS(0);
    __syncthreads();
    for (int it = 0; it < niter; it++) {
        int cur = (it & 1) * 65536;
        if (it + 1 < niter) LOADG((it + 1) << 6);
        COMPUTE(sb + cur, sb + cur + 32768);
        if (it + 1 < niter) STS(((it + 1) & 1) * 65536);
        __syncthreads();
    }

    // epilogue
    #pragma unroll
    for (int mt = 0; mt < 4; mt++) {
        int r0 = m0 + wm * 64 + mt * 16 + (lane >> 2);
        #pragma unroll
        for (int nt = 0; nt < 4; nt++) {
            int c0 = n0 + wn * 32 + nt * 8 + (lane & 3) * 2;
            #pragma unroll
            for (int i = 0; i < 4; i++) {
                int row = r0 + (i >> 1) * 8;
                int col = c0 + (i & 1);
                if (col < N) {
                    float v = acc[mt][nt][i];
                    if (HAS_BIAS) v += bias[col];
                    if (DO_GELU)  v = gelu_exact(v);
                    if (DO_RES)   v += res[(size_t)row * N + col];
                    Cm[(size_t)row * N + col] = v;
                }
            }
        }
    }
}

#define GEMM_SMEM 131072

// ---------------- launch ----------------
extern "C" void kernel_launch(void* const* d_in, const int* in_sizes, int n_in,
                              void* d_out, int out_size) {
    const int*   idx    = (const int*)  d_in[0];
    const float* wte    = (const float*)d_in[1];
    const float* pte    = (const float*)d_in[2];
    const float* ln1_s  = (const float*)d_in[3];
    const float* ln1_b  = (const float*)d_in[4];
    const float* qkv_w  = (const float*)d_in[5];
    const float* qkv_b  = (const float*)d_in[6];
    const float* proj_w = (const float*)d_in[7];
    const float* proj_b = (const float*)d_in[8];
    const float* ln2_s  = (const float*)d_in[9];
    const float* ln2_b  = (const float*)d_in[10];
    const float* w1     = (const float*)d_in[11];
    const float* b1     = (const float*)d_in[12];
    const float* w2     = (const float*)d_in[13];
    const float* b2     = (const float*)d_in[14];
    const float* lnf_s  = (const float*)d_in[15];
    const float* lnf_b  = (const float*)d_in[16];
    const float* head_w = (const float*)d_in[17];
    float* out = (float*)d_out;

    float *px, *pln, *pqkv, *patt, *pmid;
    cudaGetSymbolAddress((void**)&px,   g_x);
    cudaGetSymbolAddress((void**)&pln,  g_ln);
    cudaGetSymbolAddress((void**)&pqkv, g_qkv);
    cudaGetSymbolAddress((void**)&patt, g_att);
    cudaGetSymbolAddress((void**)&pmid, g_mid);

    cudaFuncSetAttribute(tc_gemm<1,0,0>, cudaFuncAttributeMaxDynamicSharedMemorySize, GEMM_SMEM);
    cudaFuncSetAttribute(tc_gemm<1,0,1>, cudaFuncAttributeMaxDynamicSharedMemorySize, GEMM_SMEM);
    cudaFuncSetAttribute(tc_gemm<1,1,0>, cudaFuncAttributeMaxDynamicSharedMemorySize, GEMM_SMEM);
    cudaFuncSetAttribute(tc_gemm<0,0,0>, cudaFuncAttributeMaxDynamicSharedMemorySize, GEMM_SMEM);

    embed_kernel<<<M_, 256>>>(idx, wte, pte, px);

    for (int l = 0; l < L_; l++) {
        const float* l1s = ln1_s  + (size_t)l * C_;
        const float* l1b = ln1_b  + (size_t)l * C_;
        const float* qw  = qkv_w  + (size_t)l * C_ * 3 * C_;
        const float* qb  = qkv_b  + (size_t)l * 3 * C_;
        const float* pw  = proj_w + (size_t)l * C_ * C_;
        const float* pb  = proj_b + (size_t)l * C_;
        const float* l2s = ln2_s  + (size_t)l * C_;
        const float* l2b = ln2_b  + (size_t)l * C_;
        const float* m1w = w1     + (size_t)l * C_ * F_;
        const float* m1b = b1     + (size_t)l * F_;
        const float* m2w = w2     + (size_t)l * F_ * C_;
        const float* m2b = b2     + (size_t)l * C_;

        layernorm_kernel<<<M_, 256>>>(px, l1s, l1b, pln);

        tc_gemm<1,0,0><<<dim3(M_ / 128, 3 * C_ / 128), 256, GEMM_SMEM>>>(
            pln, qw, qb, nullptr, pqkv, M_, 3 * C_, C_);

        attn_kernel<<<dim3(T_ / 4, B_ * H_), dim3(32, 4)>>>(pqkv, patt);

        tc_gemm<1,0,1><<<dim3(M_ / 128, C_ / 128), 256, GEMM_SMEM>>>(
            patt, pw, pb, px, px, M_, C_, C_);

        layernorm_kernel<<<M_, 256>>>(px, l2s, l2b, pln);

        tc_gemm<1,1,0><<<dim3(M_ / 128, F_ / 128), 256, GEMM_SMEM>>>(
            pln, m1w, m1b, nullptr, pmid, M_, F_, C_);

        tc_gemm<1,0,1><<<dim3(M_ / 128, C_ / 128), 256, GEMM_SMEM>>>(
            pmid, m2w, m2b, px, px, M_, C_, F_);
    }

    layernorm_kernel<<<M_, 256>>>(px, lnf_s, lnf_b, pln);

    tc_gemm<0,0,0><<<dim3(M_ / 128, (V_ + 127) / 128), 256, GEMM_SMEM>>>(
        pln, head_w, nullptr, nullptr, out, M_, V_, C_);
}

// round 5
// speedup vs baseline: 2.4137x; 1.2712x over previous
#include <cuda_runtime.h>
#include <cuda_bf16.h>
#include <math.h>
#include <stdint.h>

// ---------------- problem constants ----------------
#define L_  6
#define B_  2
#define T_  1024
#define C_  768
#define H_  12
#define D_  64
#define F_  3072
#define V_  50257
#define VP_ 50304              // V padded to /128
#define M_  (B_ * T_)          // 2048 rows
#define EPS_ 1e-5f

// ---------------- scratch (device globals, no runtime alloc) ----------------
__device__ float g_x  [M_ * C_];        // residual stream (fp32)
__device__ float g_qkv[M_ * 3 * C_];    // qkv (fp32, attn input)

// activation planes (bf16 hi/lo)
__device__ __nv_bfloat16 g_ln_h [M_ * C_],  g_ln_l [M_ * C_];
__device__ __nv_bfloat16 g_att_h[M_ * C_],  g_att_l[M_ * C_];
__device__ __nv_bfloat16 g_mid_h[M_ * F_],  g_mid_l[M_ * F_];

// weight planes (bf16 hi/lo), converted once per replay
__device__ __nv_bfloat16 g_qkvw_h[L_ * C_ * 3 * C_], g_qkvw_l[L_ * C_ * 3 * C_];
__device__ __nv_bfloat16 g_projw_h[L_ * C_ * C_],    g_projw_l[L_ * C_ * C_];
__device__ __nv_bfloat16 g_w1_h  [L_ * C_ * F_],     g_w1_l  [L_ * C_ * F_];
__device__ __nv_bfloat16 g_w2_h  [L_ * F_ * C_],     g_w2_l  [L_ * F_ * C_];
__device__ __nv_bfloat16 g_hw_h  [C_ * VP_],         g_hw_l  [C_ * VP_];

// ---------------- helpers ----------------
__device__ __forceinline__ uint32_t smem_u32(const void* p) {
    uint32_t a;
    asm("{ .reg .u64 t; cvta.to.shared.u64 t, %1; cvt.u32.u64 %0, t; }" : "=r"(a) : "l"(p));
    return a;
}
__device__ __forceinline__ void cp16(uint32_t dst, const void* src) {
    asm volatile("cp.async.cg.shared.global [%0], [%1], 16;" :: "r"(dst), "l"(src));
}
__device__ __forceinline__ void cp_commit() {
    asm volatile("cp.async.commit_group;" ::: "memory");
}
__device__ __forceinline__ void ldsm_x4(uint32_t* r, uint32_t a) {
    asm volatile("ldmatrix.sync.aligned.m8n8.x4.shared.b16 {%0,%1,%2,%3}, [%4];"
        : "=r"(r[0]), "=r"(r[1]), "=r"(r[2]), "=r"(r[3]) : "r"(a));
}
__device__ __forceinline__ void ldsm_x2t(uint32_t* r, uint32_t a) {
    asm volatile("ldmatrix.sync.aligned.m8n8.x2.trans.shared.b16 {%0,%1}, [%2];"
        : "=r"(r[0]), "=r"(r[1]) : "r"(a));
}
__device__ __forceinline__ void mma16816(float* d, const uint32_t* a, const uint32_t* b) {
    asm volatile("mma.sync.aligned.m16n8k16.row.col.f32.bf16.bf16.f32 "
        "{%0,%1,%2,%3}, {%4,%5,%6,%7}, {%8,%9}, {%0,%1,%2,%3};"
        : "+f"(d[0]), "+f"(d[1]), "+f"(d[2]), "+f"(d[3])
        : "r"(a[0]), "r"(a[1]), "r"(a[2]), "r"(a[3]), "r"(b[0]), "r"(b[1]));
}
__device__ __forceinline__ void split1(float x, __nv_bfloat16& h, __nv_bfloat16& l) {
    h = __float2bfloat16(x);
    l = __float2bfloat16(x - __bfloat162float(h));
}
__device__ __forceinline__ float gelu_exact(float v) {
    return 0.5f * v * (1.0f + erff(v * 0.70710678118654752f));
}

// ---------------- weight conversion ----------------
__global__ void convert_kernel(const float* __restrict__ src,
                               __nv_bfloat16* __restrict__ hi,
                               __nv_bfloat16* __restrict__ lo, int n4) {
    int e = blockIdx.x * blockDim.x + threadIdx.x;
    if (e >= n4) return;
    float4 v = *(const float4*)(src + (size_t)e * 4);
    __nv_bfloat16 h[4], l[4];
    split1(v.x, h[0], l[0]); split1(v.y, h[1], l[1]);
    split1(v.z, h[2], l[2]); split1(v.w, h[3], l[3]);
    *(__nv_bfloat162*)(hi + (size_t)e * 4)     = *(__nv_bfloat162*)&h[0];
    *(__nv_bfloat162*)(hi + (size_t)e * 4 + 2) = *(__nv_bfloat162*)&h[2];
    *(__nv_bfloat162*)(lo + (size_t)e * 4)     = *(__nv_bfloat162*)&l[0];
    *(__nv_bfloat162*)(lo + (size_t)e * 4 + 2) = *(__nv_bfloat162*)&l[2];
}

// head_w [C_ x V_] -> padded planes [C_ x VP_]
__global__ void convert_head_kernel(const float* __restrict__ src,
                                    __nv_bfloat16* __restrict__ hi,
                                    __nv_bfloat16* __restrict__ lo) {
    int e = blockIdx.x * blockDim.x + threadIdx.x;   // groups of 4 in padded layout
    if (e >= C_ * (VP_ / 4)) return;
    int row = e / (VP_ / 4);
    int c0  = (e % (VP_ / 4)) * 4;
    __nv_bfloat16 h[4], l[4];
    #pragma unroll
    for (int j = 0; j < 4; j++) {
        int c = c0 + j;
        float v = (c < V_) ? src[(size_t)row * V_ + c] : 0.0f;
        split1(v, h[j], l[j]);
    }
    size_t o = (size_t)row * VP_ + c0;
    *(__nv_bfloat162*)(hi + o)     = *(__nv_bfloat162*)&h[0];
    *(__nv_bfloat162*)(hi + o + 2) = *(__nv_bfloat162*)&h[2];
    *(__nv_bfloat162*)(lo + o)     = *(__nv_bfloat162*)&l[0];
    *(__nv_bfloat162*)(lo + o + 2) = *(__nv_bfloat162*)&l[2];
}

// ---------------- embedding ----------------
__global__ void embed_kernel(const int* __restrict__ idx,
                             const float* __restrict__ wte,
                             const float* __restrict__ pte,
                             float* __restrict__ x) {
    int r = blockIdx.x;
    int t = r % T_;
    int tok = idx[r];
    const float* wrow = wte + (size_t)tok * C_;
    const float* prow = pte + (size_t)t * C_;
    float* xr = x + (size_t)r * C_;
    for (int c = threadIdx.x; c < C_; c += blockDim.x)
        xr[c] = wrow[c] + prow[c];
}

// ---------------- layernorm -> bf16 hi/lo planes ----------------
__global__ void layernorm_kernel(const float* __restrict__ x,
                                 const float* __restrict__ sc,
                                 const float* __restrict__ bi,
                                 __nv_bfloat16* __restrict__ yh,
                                 __nv_bfloat16* __restrict__ yl) {
    __shared__ float sh1[256];
    __shared__ float sh2[256];
    int r = blockIdx.x;
    int tid = threadIdx.x;
    const float* xr = x + (size_t)r * C_;
    float v0 = xr[tid], v1 = xr[tid + 256], v2 = xr[tid + 512];
    float s  = v0 + v1 + v2;
    float ss = v0 * v0 + v1 * v1 + v2 * v2;
    sh1[tid] = s; sh2[tid] = ss;
    __syncthreads();
    for (int off = 128; off > 0; off >>= 1) {
        if (tid < off) { sh1[tid] += sh1[tid + off]; sh2[tid] += sh2[tid + off]; }
        __syncthreads();
    }
    float mu  = sh1[0] * (1.0f / C_);
    float var = sh2[0] * (1.0f / C_) - mu * mu;
    float rstd = rsqrtf(var + EPS_);
    size_t base = (size_t)r * C_;
    #pragma unroll
    for (int q = 0; q < 3; q++) {
        int c = tid + q * 256;
        float v = (q == 0 ? v0 : (q == 1 ? v1 : v2));
        float y = (v - mu) * rstd * sc[c] + bi[c];
        __nv_bfloat16 h, l;
        split1(y, h, l);
        yh[base + c] = h;
        yl[base + c] = l;
    }
}

// ---------------- attention (2 keys / iter) -> bf16 planes ----------------
__global__ void attn_kernel(const float* __restrict__ qkv,
                            __nv_bfloat16* __restrict__ oh,
                            __nv_bfloat16* __restrict__ ol) {
    int lane = threadIdx.x;
    int q = blockIdx.x * blockDim.y + threadIdx.y;
    int bh = blockIdx.y;
    int b = bh / H_, h = bh % H_;

    const float* base = qkv + (size_t)b * T_ * 3 * C_;
    const float* qp = base + (size_t)q * 3 * C_ + h * D_;
    float q0 = qp[lane]      * 0.125f;
    float q1 = qp[lane + 32] * 0.125f;

    float m = -3.0e38f, l = 0.0f, a0 = 0.0f, a1 = 0.0f;
    int j = 0;
    for (; j + 1 <= q; j += 2) {
        const float* kp0 = base + (size_t)j * 3 * C_ + C_ + h * D_;
        const float* kp1 = kp0 + 3 * C_;
        float s0 = q0 * kp0[lane] + q1 * kp0[lane + 32];
        float s1 = q0 * kp1[lane] + q1 * kp1[lane + 32];
        #pragma unroll
        for (int off = 16; off > 0; off >>= 1) {
            s0 += __shfl_xor_sync(0xffffffff, s0, off);
            s1 += __shfl_xor_sync(0xffffffff, s1, off);
        }
        float mn = fmaxf(m, fmaxf(s0, s1));
        float corr = __expf(m - mn);
        float p0 = __expf(s0 - mn);
        float p1 = __expf(s1 - mn);
        const float* vp0 = base + (size_t)j * 3 * C_ + 2 * C_ + h * D_;
        const float* vp1 = vp0 + 3 * C_;
        l  = l  * corr + p0 + p1;
        a0 = a0 * corr + p0 * vp0[lane]      + p1 * vp1[lane];
        a1 = a1 * corr + p0 * vp0[lane + 32] + p1 * vp1[lane + 32];
        m = mn;
    }
    if (j <= q) {
        const float* kp = base + (size_t)j * 3 * C_ + C_ + h * D_;
        float s = q0 * kp[lane] + q1 * kp[lane + 32];
        #pragma unroll
        for (int off = 16; off > 0; off >>= 1)
            s += __shfl_xor_sync(0xffffffff, s, off);
        float mn = fmaxf(m, s);
        float corr = __expf(m - mn);
        float p = __expf(s - mn);
        const float* vp = base + (size_t)j * 3 * C_ + 2 * C_ + h * D_;
        l  = l  * corr + p;
        a0 = a0 * corr + p * vp[lane];
        a1 = a1 * corr + p * vp[lane + 32];
        m = mn;
    }
    float inv = 1.0f / l;
    size_t o = (size_t)(b * T_ + q) * C_ + h * D_;
    __nv_bfloat16 hh, ll;
    split1(a0 * inv, hh, ll); oh[o + lane] = hh;      ol[o + lane] = ll;
    split1(a1 * inv, hh, ll); oh[o + lane + 32] = hh; ol[o + lane + 32] = ll;
}

// ================= split-bf16 mma.sync GEMM, cp.async pipeline =================
// Tile 128x128, BK=64, 256 threads, double buffer (128KB).
// Per buffer: Ahi[128x64] @0, Alo @16384, Bhi[64x128] @32768, Blo @49152.

template<int HAS_BIAS, int DO_GELU, int DO_RES, int WRITE_PLANES>
__global__ __launch_bounds__(256, 1) void tc_gemm(
        const __nv_bfloat16* __restrict__ Ahi, const __nv_bfloat16* __restrict__ Alo,
        const __nv_bfloat16* __restrict__ Bhi, const __nv_bfloat16* __restrict__ Blo,
        const float* __restrict__ bias, const float* __restrict__ res,
        float* __restrict__ Cf,
        __nv_bfloat16* __restrict__ Chi, __nv_bfloat16* __restrict__ Clo,
        int M, int Nb, int Nc, int K) {
    extern __shared__ __align__(1024) char dsm[];
    uint32_t sb = smem_u32(dsm);
    const int tid = threadIdx.x, lane = tid & 31, wid = tid >> 5;
    const int wm = wid >> 2, wn = wid & 3;
    const int m0 = blockIdx.x * 128, n0 = blockIdx.y * 128;
    const int niter = K >> 6;

    float acc[4][4][4];
    #pragma unroll
    for (int a = 0; a < 4; a++)
        #pragma unroll
        for (int b = 0; b < 4; b++)
            #pragma unroll
            for (int c = 0; c < 4; c++) acc[a][b][c] = 0.0f;

    auto PREFETCH = [&](int it) {
        int k0 = it << 6;
        uint32_t buf = sb + (it & 1) * 65536;
        #pragma unroll
        for (int i = 0; i < 4; i++) {
            int e = tid + 256 * i;
            int r = e >> 3, u = e & 7;
            uint32_t d = buf + (uint32_t)(r * 128 + ((u ^ (r & 7)) << 4));
            size_t so = (size_t)(m0 + r) * K + k0 + u * 8;
            cp16(d, Ahi + so);
            cp16(d + 16384, Alo + so);
        }
        #pragma unroll
        for (int i = 0; i < 4; i++) {
            int e = tid + 256 * i;
            int kr = e >> 4, u = e & 15;
            uint32_t d = buf + 32768 + (uint32_t)(kr * 256 + ((u ^ (kr & 7)) << 4));
            size_t so = (size_t)(k0 + kr) * Nb + n0 + u * 8;
            cp16(d, Bhi + so);
            cp16(d + 16384, Blo + so);
        }
        cp_commit();
    };

    auto COMPUTE = [&](int bufi) {
        uint32_t aBase = sb + bufi * 65536;
        uint32_t bBase = aBase + 32768;
        #pragma unroll
        for (int ks = 0; ks < 4; ks++) {
            uint32_t ah[4][4], alr[4][4];
            #pragma unroll
            for (int mt = 0; mt < 4; mt++) {
                int r = wm * 64 + mt * 16 + (lane & 15);
                int c = ks * 2 + (lane >> 4);
                uint32_t off = (uint32_t)(r * 128 + ((c ^ (r & 7)) << 4));
                ldsm_x4(ah[mt],  aBase + off);
                ldsm_x4(alr[mt], aBase + 16384 + off);
            }
            uint32_t bh[4][2], blr[4][2];
            #pragma unroll
            for (int nt = 0; nt < 4; nt++) {
                int kt = ks * 16 + (lane & 15);
                int c = wn * 4 + nt;
                uint32_t off = (uint32_t)(kt * 256 + ((c ^ (kt & 7)) << 4));
                ldsm_x2t(bh[nt],  bBase + off);
                ldsm_x2t(blr[nt], bBase + 16384 + off);
            }
            #pragma unroll
            for (int mt = 0; mt < 4; mt++)
                #pragma unroll
                for (int nt = 0; nt < 4; nt++) {
                    mma16816(acc[mt][nt], ah[mt],  bh[nt]);
                    mma16816(acc[mt][nt], ah[mt],  blr[nt]);
                    mma16816(acc[mt][nt], alr[mt], bh[nt]);
                }
        }
    };

    PREFETCH(0);
    for (int it = 0; it < niter; it++) {
        if (it + 1 < niter) {
            PREFETCH(it + 1);
            asm volatile("cp.async.wait_group 1;" ::: "memory");
        } else {
            asm volatile("cp.async.wait_group 0;" ::: "memory");
        }
        __syncthreads();
        COMPUTE(it & 1);
        __syncthreads();
    }

    // epilogue
    #pragma unroll
    for (int mt = 0; mt < 4; mt++) {
        int r0 = m0 + wm * 64 + mt * 16 + (lane >> 2);
        #pragma unroll
        for (int nt = 0; nt < 4; nt++) {
            int c0 = n0 + wn * 32 + nt * 8 + (lane & 3) * 2;
            float v[4];
            #pragma unroll
            for (int i = 0; i < 4; i++) {
                v[i] = acc[mt][nt][i];
                int col = c0 + (i & 1);
                if (HAS_BIAS && col < Nc) v[i] += bias[col];
                if (DO_GELU) v[i] = gelu_exact(v[i]);
            }
            if (WRITE_PLANES) {
                #pragma unroll
                for (int half = 0; half < 2; half++) {
                    int row = r0 + half * 8;
                    __nv_bfloat16 h0, l0, h1, l1;
                    split1(v[half * 2],     h0, l0);
                    split1(v[half * 2 + 1], h1, l1);
                    size_t o = (size_t)row * Nc + c0;
                    *(__nv_bfloat162*)(Chi + o) = __halves2bfloat162(h0, h1);
                    *(__nv_bfloat162*)(Clo + o) = __halves2bfloat162(l0, l1);
                }
            } else {
                #pragma unroll
                for (int i = 0; i < 4; i++) {
                    int row = r0 + (i >> 1) * 8;
                    int col = c0 + (i & 1);
                    if (col < Nc) {
                        float w = v[i];
                        if (DO_RES) w += res[(size_t)row * Nc + col];
                        Cf[(size_t)row * Nc + col] = w;
                    }
                }
            }
        }
    }
}

#define GEMM_SMEM 131072

// ---------------- launch ----------------
extern "C" void kernel_launch(void* const* d_in, const int* in_sizes, int n_in,
                              void* d_out, int out_size) {
    const int*   idx    = (const int*)  d_in[0];
    const float* wte    = (const float*)d_in[1];
    const float* pte    = (const float*)d_in[2];
    const float* ln1_s  = (const float*)d_in[3];
    const float* ln1_b  = (const float*)d_in[4];
    const float* qkv_w  = (const float*)d_in[5];
    const float* qkv_b  = (const float*)d_in[6];
    const float* proj_w = (const float*)d_in[7];
    const float* proj_b = (const float*)d_in[8];
    const float* ln2_s  = (const float*)d_in[9];
    const float* ln2_b  = (const float*)d_in[10];
    const float* w1     = (const float*)d_in[11];
    const float* b1     = (const float*)d_in[12];
    const float* w2     = (const float*)d_in[13];
    const float* b2     = (const float*)d_in[14];
    const float* lnf_s  = (const float*)d_in[15];
    const float* lnf_b  = (const float*)d_in[16];
    const float* head_w = (const float*)d_in[17];
    float* out = (float*)d_out;

    float *px, *pqkv;
    cudaGetSymbolAddress((void**)&px,   g_x);
    cudaGetSymbolAddress((void**)&pqkv, g_qkv);
    __nv_bfloat16 *lnh, *lnl, *ath, *atl, *mdh, *mdl;
    cudaGetSymbolAddress((void**)&lnh, g_ln_h);  cudaGetSymbolAddress((void**)&lnl, g_ln_l);
    cudaGetSymbolAddress((void**)&ath, g_att_h); cudaGetSymbolAddress((void**)&atl, g_att_l);
    cudaGetSymbolAddress((void**)&mdh, g_mid_h); cudaGetSymbolAddress((void**)&mdl, g_mid_l);
    __nv_bfloat16 *qwh, *qwl, *pwh, *pwl, *w1h, *w1l, *w2h, *w2l, *hwh, *hwl;
    cudaGetSymbolAddress((void**)&qwh, g_qkvw_h); cudaGetSymbolAddress((void**)&qwl, g_qkvw_l);
    cudaGetSymbolAddress((void**)&pwh, g_projw_h); cudaGetSymbolAddress((void**)&pwl, g_projw_l);
    cudaGetSymbolAddress((void**)&w1h, g_w1_h);   cudaGetSymbolAddress((void**)&w1l, g_w1_l);
    cudaGetSymbolAddress((void**)&w2h, g_w2_h);   cudaGetSymbolAddress((void**)&w2l, g_w2_l);
    cudaGetSymbolAddress((void**)&hwh, g_hw_h);   cudaGetSymbolAddress((void**)&hwl, g_hw_l);

    cudaFuncSetAttribute(tc_gemm<1,0,0,0>, cudaFuncAttributeMaxDynamicSharedMemorySize, GEMM_SMEM);
    cudaFuncSetAttribute(tc_gemm<1,0,1,0>, cudaFuncAttributeMaxDynamicSharedMemorySize, GEMM_SMEM);
    cudaFuncSetAttribute(tc_gemm<1,1,0,1>, cudaFuncAttributeMaxDynamicSharedMemorySize, GEMM_SMEM);
    cudaFuncSetAttribute(tc_gemm<0,0,0,0>, cudaFuncAttributeMaxDynamicSharedMemorySize, GEMM_SMEM);

    // ---- weight conversion (once per replay) ----
    {
        int n;
        n = L_ * C_ * 3 * C_ / 4;
        convert_kernel<<<(n + 255) / 256, 256>>>(qkv_w, qwh, qwl, n);
        n = L_ * C_ * C_ / 4;
        convert_kernel<<<(n + 255) / 256, 256>>>(proj_w, pwh, pwl, n);
        n = L_ * C_ * F_ / 4;
        convert_kernel<<<(n + 255) / 256, 256>>>(w1, w1h, w1l, n);
        n = L_ * F_ * C_ / 4;
        convert_kernel<<<(n + 255) / 256, 256>>>(w2, w2h, w2l, n);
        n = C_ * VP_ / 4;
        convert_head_kernel<<<(n + 255) / 256, 256>>>(head_w, hwh, hwl);
    }

    embed_kernel<<<M_, 256>>>(idx, wte, pte, px);

    for (int l = 0; l < L_; l++) {
        const __nv_bfloat16* qwh_l = qwh + (size_t)l * C_ * 3 * C_;
        const __nv_bfloat16* qwl_l = qwl + (size_t)l * C_ * 3 * C_;
        const __nv_bfloat16* pwh_l = pwh + (size_t)l * C_ * C_;
        const __nv_bfloat16* pwl_l = pwl + (size_t)l * C_ * C_;
        const __nv_bfloat16* w1h_l = w1h + (size_t)l * C_ * F_;
        const __nv_bfloat16* w1l_l = w1l + (size_t)l * C_ * F_;
        const __nv_bfloat16* w2h_l = w2h + (size_t)l * F_ * C_;
        const __nv_bfloat16* w2l_l = w2l + (size_t)l * F_ * C_;

        layernorm_kernel<<<M_, 256>>>(px, ln1_s + (size_t)l * C_, ln1_b + (size_t)l * C_, lnh, lnl);

        // qkv = ln @ qkv_w + qkv_b   [2048 x 2304] fp32
        tc_gemm<1,0,0,0><<<dim3(M_ / 128, 3 * C_ / 128), 256, GEMM_SMEM>>>(
            lnh, lnl, qwh_l, qwl_l, qkv_b + (size_t)l * 3 * C_, nullptr,
            pqkv, nullptr, nullptr, M_, 3 * C_, 3 * C_, C_);

        attn_kernel<<<dim3(T_ / 4, B_ * H_), dim3(32, 4)>>>(pqkv, ath, atl);

        // x = x + att @ proj_w + proj_b
        tc_gemm<1,0,1,0><<<dim3(M_ / 128, C_ / 128), 256, GEMM_SMEM>>>(
            ath, atl, pwh_l, pwl_l, proj_b + (size_t)l * C_, px,
            px, nullptr, nullptr, M_, C_, C_, C_);

        layernorm_kernel<<<M_, 256>>>(px, ln2_s + (size_t)l * C_, ln2_b + (size_t)l * C_, lnh, lnl);

        // mid = gelu(ln2 @ w1 + b1) -> planes
        tc_gemm<1,1,0,1><<<dim3(M_ / 128, F_ / 128), 256, GEMM_SMEM>>>(
            lnh, lnl, w1h_l, w1l_l, b1 + (size_t)l * F_, nullptr,
            nullptr, mdh, mdl, M_, F_, F_, C_);

        // x = x + mid @ w2 + b2
        tc_gemm<1,0,1,0><<<dim3(M_ / 128, C_ / 128), 256, GEMM_SMEM>>>(
            mdh, mdl, w2h_l, w2l_l, b2 + (size_t)l * C_, px,
            px, nullptr, nullptr, M_, C_, C_, F_);
    }

    layernorm_kernel<<<M_, 256>>>(px, lnf_s, lnf_b, lnh, lnl);

    // logits = lnf @ head_w   [2048 x 50257], B padded to 50304
    tc_gemm<0,0,0,0><<<dim3(M_ / 128, VP_ / 128), 256, GEMM_SMEM>>>(
        lnh, lnl, hwh, hwl, nullptr, nullptr,
        out, nullptr, nullptr, M_, VP_, V_, C_);
}

// round 6
// speedup vs baseline: 3.0376x; 1.2585x over previous
#include <cuda_runtime.h>
#include <cuda_bf16.h>
#include <cuda_fp16.h>
#include <math.h>
#include <stdint.h>

// ---------------- problem constants ----------------
#define L_  6
#define B_  2
#define T_  1024
#define C_  768
#define H_  12
#define D_  64
#define F_  3072
#define V_  50257
#define VP_ 50304              // V padded to /128
#define M_  (B_ * T_)          // 2048 rows
#define EPS_ 1e-5f

// ---------------- scratch (device globals, no runtime alloc) ----------------
__device__ float g_x  [M_ * C_];        // residual stream (fp32)
__device__ float g_qkv[M_ * 3 * C_];    // qkv (fp32, attn input)

// activation planes
__device__ __nv_bfloat16 g_ln_h [M_ * C_],  g_ln_l [M_ * C_];
__device__ __nv_bfloat16 g_att_h[M_ * C_],  g_att_l[M_ * C_];
__device__ __nv_bfloat16 g_mid_h[M_ * F_],  g_mid_l[M_ * F_];
__device__ __half        g_lnf16[M_ * C_];  // final LN, fp16 single plane

// weight planes, converted once per replay
__device__ __nv_bfloat16 g_qkvw_h[L_ * C_ * 3 * C_], g_qkvw_l[L_ * C_ * 3 * C_];
__device__ __nv_bfloat16 g_projw_h[L_ * C_ * C_],    g_projw_l[L_ * C_ * C_];
__device__ __nv_bfloat16 g_w1_h  [L_ * C_ * F_],     g_w1_l  [L_ * C_ * F_];
__device__ __nv_bfloat16 g_w2_h  [L_ * F_ * C_],     g_w2_l  [L_ * F_ * C_];
__device__ __half        g_hw_h  [C_ * VP_],         g_hw_l  [C_ * VP_];

// ---------------- helpers ----------------
__device__ __forceinline__ uint32_t smem_u32(const void* p) {
    uint32_t a;
    asm("{ .reg .u64 t; cvta.to.shared.u64 t, %1; cvt.u32.u64 %0, t; }" : "=r"(a) : "l"(p));
    return a;
}
__device__ __forceinline__ void cp16(uint32_t dst, const void* src) {
    asm volatile("cp.async.cg.shared.global [%0], [%1], 16;" :: "r"(dst), "l"(src));
}
__device__ __forceinline__ void cp_commit() {
    asm volatile("cp.async.commit_group;" ::: "memory");
}
__device__ __forceinline__ void ldsm_x4(uint32_t* r, uint32_t a) {
    asm volatile("ldmatrix.sync.aligned.m8n8.x4.shared.b16 {%0,%1,%2,%3}, [%4];"
        : "=r"(r[0]), "=r"(r[1]), "=r"(r[2]), "=r"(r[3]) : "r"(a));
}
__device__ __forceinline__ void ldsm_x2t(uint32_t* r, uint32_t a) {
    asm volatile("ldmatrix.sync.aligned.m8n8.x2.trans.shared.b16 {%0,%1}, [%2];"
        : "=r"(r[0]), "=r"(r[1]) : "r"(a));
}
__device__ __forceinline__ void mma_bf16(float* d, const uint32_t* a, const uint32_t* b) {
    asm volatile("mma.sync.aligned.m16n8k16.row.col.f32.bf16.bf16.f32 "
        "{%0,%1,%2,%3}, {%4,%5,%6,%7}, {%8,%9}, {%0,%1,%2,%3};"
        : "+f"(d[0]), "+f"(d[1]), "+f"(d[2]), "+f"(d[3])
        : "r"(a[0]), "r"(a[1]), "r"(a[2]), "r"(a[3]), "r"(b[0]), "r"(b[1]));
}
__device__ __forceinline__ void mma_f16(float* d, const uint32_t* a, const uint32_t* b) {
    asm volatile("mma.sync.aligned.m16n8k16.row.col.f32.f16.f16.f32 "
        "{%0,%1,%2,%3}, {%4,%5,%6,%7}, {%8,%9}, {%0,%1,%2,%3};"
        : "+f"(d[0]), "+f"(d[1]), "+f"(d[2]), "+f"(d[3])
        : "r"(a[0]), "r"(a[1]), "r"(a[2]), "r"(a[3]), "r"(b[0]), "r"(b[1]));
}
__device__ __forceinline__ void split1(float x, __nv_bfloat16& h, __nv_bfloat16& l) {
    h = __float2bfloat16(x);
    l = __float2bfloat16(x - __bfloat162float(h));
}
__device__ __forceinline__ void split1h(float x, __half& h, __half& l) {
    h = __float2half_rn(x);
    l = __float2half_rn(x - __half2float(h));
}
__device__ __forceinline__ float gelu_exact(float v) {
    return 0.5f * v * (1.0f + erff(v * 0.70710678118654752f));
}

// ---------------- weight conversion ----------------
__global__ void convert_kernel(const float* __restrict__ src,
                               __nv_bfloat16* __restrict__ hi,
                               __nv_bfloat16* __restrict__ lo, int n4) {
    int e = blockIdx.x * blockDim.x + threadIdx.x;
    if (e >= n4) return;
    float4 v = *(const float4*)(src + (size_t)e * 4);
    __nv_bfloat16 h[4], l[4];
    split1(v.x, h[0], l[0]); split1(v.y, h[1], l[1]);
    split1(v.z, h[2], l[2]); split1(v.w, h[3], l[3]);
    *(__nv_bfloat162*)(hi + (size_t)e * 4)     = *(__nv_bfloat162*)&h[0];
    *(__nv_bfloat162*)(hi + (size_t)e * 4 + 2) = *(__nv_bfloat162*)&h[2];
    *(__nv_bfloat162*)(lo + (size_t)e * 4)     = *(__nv_bfloat162*)&l[0];
    *(__nv_bfloat162*)(lo + (size_t)e * 4 + 2) = *(__nv_bfloat162*)&l[2];
}

// head_w [C_ x V_] -> padded fp16 planes [C_ x VP_]
__global__ void convert_head_kernel(const float* __restrict__ src,
                                    __half* __restrict__ hi,
                                    __half* __restrict__ lo) {
    int e = blockIdx.x * blockDim.x + threadIdx.x;
    if (e >= C_ * (VP_ / 4)) return;
    int row = e / (VP_ / 4);
    int c0  = (e % (VP_ / 4)) * 4;
    __half h[4], l[4];
    #pragma unroll
    for (int j = 0; j < 4; j++) {
        int c = c0 + j;
        float v = (c < V_) ? src[(size_t)row * V_ + c] : 0.0f;
        split1h(v, h[j], l[j]);
    }
    size_t o = (size_t)row * VP_ + c0;
    *(__half2*)(hi + o)     = *(__half2*)&h[0];
    *(__half2*)(hi + o + 2) = *(__half2*)&h[2];
    *(__half2*)(lo + o)     = *(__half2*)&l[0];
    *(__half2*)(lo + o + 2) = *(__half2*)&l[2];
}

// ---------------- embedding ----------------
__global__ void embed_kernel(const int* __restrict__ idx,
                             const float* __restrict__ wte,
                             const float* __restrict__ pte,
                             float* __restrict__ x) {
    int r = blockIdx.x;
    int t = r % T_;
    int tok = idx[r];
    const float* wrow = wte + (size_t)tok * C_;
    const float* prow = pte + (size_t)t * C_;
    float* xr = x + (size_t)r * C_;
    for (int c = threadIdx.x; c < C_; c += blockDim.x)
        xr[c] = wrow[c] + prow[c];
}

// ---------------- layernorm -> bf16 hi/lo planes ----------------
__global__ void layernorm_kernel(const float* __restrict__ x,
                                 const float* __restrict__ sc,
                                 const float* __restrict__ bi,
                                 __nv_bfloat16* __restrict__ yh,
                                 __nv_bfloat16* __restrict__ yl) {
    __shared__ float sh1[256];
    __shared__ float sh2[256];
    int r = blockIdx.x;
    int tid = threadIdx.x;
    const float* xr = x + (size_t)r * C_;
    float v0 = xr[tid], v1 = xr[tid + 256], v2 = xr[tid + 512];
    float s  = v0 + v1 + v2;
    float ss = v0 * v0 + v1 * v1 + v2 * v2;
    sh1[tid] = s; sh2[tid] = ss;
    __syncthreads();
    for (int off = 128; off > 0; off >>= 1) {
        if (tid < off) { sh1[tid] += sh1[tid + off]; sh2[tid] += sh2[tid + off]; }
        __syncthreads();
    }
    float mu  = sh1[0] * (1.0f / C_);
    float var = sh2[0] * (1.0f / C_) - mu * mu;
    float rstd = rsqrtf(var + EPS_);
    size_t base = (size_t)r * C_;
    #pragma unroll
    for (int q = 0; q < 3; q++) {
        int c = tid + q * 256;
        float v = (q == 0 ? v0 : (q == 1 ? v1 : v2));
        float y = (v - mu) * rstd * sc[c] + bi[c];
        __nv_bfloat16 h, l;
        split1(y, h, l);
        yh[base + c] = h;
        yl[base + c] = l;
    }
}

// ---------------- final layernorm -> single fp16 plane ----------------
__global__ void layernorm_f16_kernel(const float* __restrict__ x,
                                     const float* __restrict__ sc,
                                     const float* __restrict__ bi,
                                     __half* __restrict__ y) {
    __shared__ float sh1[256];
    __shared__ float sh2[256];
    int r = blockIdx.x;
    int tid = threadIdx.x;
    const float* xr = x + (size_t)r * C_;
    float v0 = xr[tid], v1 = xr[tid + 256], v2 = xr[tid + 512];
    float s  = v0 + v1 + v2;
    float ss = v0 * v0 + v1 * v1 + v2 * v2;
    sh1[tid] = s; sh2[tid] = ss;
    __syncthreads();
    for (int off = 128; off > 0; off >>= 1) {
        if (tid < off) { sh1[tid] += sh1[tid + off]; sh2[tid] += sh2[tid + off]; }
        __syncthreads();
    }
    float mu  = sh1[0] * (1.0f / C_);
    float var = sh2[0] * (1.0f / C_) - mu * mu;
    float rstd = rsqrtf(var + EPS_);
    size_t base = (size_t)r * C_;
    #pragma unroll
    for (int q = 0; q < 3; q++) {
        int c = tid + q * 256;
        float v = (q == 0 ? v0 : (q == 1 ? v1 : v2));
        y[base + c] = __float2half_rn((v - mu) * rstd * sc[c] + bi[c]);
    }
}

// ---------------- attention (4 keys/iter, float2 lanes) -> bf16 planes ----------------
__global__ void attn_kernel(const float* __restrict__ qkv,
                            __nv_bfloat16* __restrict__ oh,
                            __nv_bfloat16* __restrict__ ol) {
    int lane = threadIdx.x;
    int q = blockIdx.x * blockDim.y + threadIdx.y;
    int bh = blockIdx.y;
    int b = bh / H_, h = bh % H_;

    const float* base = qkv + (size_t)b * T_ * 3 * C_;
    float2 q2 = *(const float2*)(base + (size_t)q * 3 * C_ + h * D_ + 2 * lane);
    float q0 = q2.x * 0.125f, q1 = q2.y * 0.125f;

    float m = -3.0e38f, l = 0.0f, a0 = 0.0f, a1 = 0.0f;
    int j = 0;
    const float* kbase = base + C_ + h * D_ + 2 * lane;
    const float* vbase = base + 2 * C_ + h * D_ + 2 * lane;
    for (; j + 3 <= q; j += 4) {
        float s[4];
        #pragma unroll
        for (int u = 0; u < 4; u++) {
            float2 k2 = *(const float2*)(kbase + (size_t)(j + u) * 3 * C_);
            s[u] = q0 * k2.x + q1 * k2.y;
        }
        #pragma unroll
        for (int off = 16; off > 0; off >>= 1) {
            #pragma unroll
            for (int u = 0; u < 4; u++)
                s[u] += __shfl_xor_sync(0xffffffff, s[u], off);
        }
        float mn = fmaxf(fmaxf(s[0], s[1]), fmaxf(s[2], s[3]));
        mn = fmaxf(m, mn);
        float corr = __expf(m - mn);
        l *= corr; a0 *= corr; a1 *= corr;
        #pragma unroll
        for (int u = 0; u < 4; u++) {
            float p = __expf(s[u] - mn);
            float2 v2 = *(const float2*)(vbase + (size_t)(j + u) * 3 * C_);
            l  += p;
            a0 += p * v2.x;
            a1 += p * v2.y;
        }
        m = mn;
    }
    for (; j <= q; j++) {
        float2 k2 = *(const float2*)(kbase + (size_t)j * 3 * C_);
        float s = q0 * k2.x + q1 * k2.y;
        #pragma unroll
        for (int off = 16; off > 0; off >>= 1)
            s += __shfl_xor_sync(0xffffffff, s, off);
        float mn = fmaxf(m, s);
        float corr = __expf(m - mn);
        float p = __expf(s - mn);
        float2 v2 = *(const float2*)(vbase + (size_t)j * 3 * C_);
        l  = l  * corr + p;
        a0 = a0 * corr + p * v2.x;
        a1 = a1 * corr + p * v2.y;
        m = mn;
    }
    float inv = 1.0f / l;
    size_t o = (size_t)(b * T_ + q) * C_ + h * D_ + 2 * lane;
    __nv_bfloat16 h0, l0, h1, l1;
    split1(a0 * inv, h0, l0);
    split1(a1 * inv, h1, l1);
    *(__nv_bfloat162*)(oh + o) = __halves2bfloat162(h0, h1);
    *(__nv_bfloat162*)(ol + o) = __halves2bfloat162(l0, l1);
}

// ================= 3-term split-bf16 GEMM, 3-stage cp.async =================
// Tile 128x128, BK=64, 256 threads.
// Stage (64KB): Ah @0, Al @16384, Bh @32768, Bl @49152. 3 stages = 192KB.

#define STG3 65536

template<int HAS_BIAS, int DO_GELU, int DO_RES, int WRITE_PLANES>
__global__ __launch_bounds__(256, 1) void tc_gemm(
        const __nv_bfloat16* __restrict__ Ahi, const __nv_bfloat16* __restrict__ Alo,
        const __nv_bfloat16* __restrict__ Bhi, const __nv_bfloat16* __restrict__ Blo,
        const float* __restrict__ bias, const float* __restrict__ res,
        float* __restrict__ Cf,
        __nv_bfloat16* __restrict__ Chi, __nv_bfloat16* __restrict__ Clo,
        int M, int Nb, int Nc, int K) {
    extern __shared__ __align__(1024) char dsm[];
    uint32_t sb = smem_u32(dsm);
    const int tid = threadIdx.x, lane = tid & 31, wid = tid >> 5;
    const int wm = wid >> 2, wn = wid & 3;
    const int m0 = blockIdx.x * 128, n0 = blockIdx.y * 128;
    const int niter = K >> 6;

    float acc[4][4][4];
    #pragma unroll
    for (int a = 0; a < 4; a++)
        #pragma unroll
        for (int b = 0; b < 4; b++)
            #pragma unroll
            for (int c = 0; c < 4; c++) acc[a][b][c] = 0.0f;

    auto PREFETCH = [&](int it) {
        if (it < niter) {
            int k0 = it << 6;
            uint32_t buf = sb + (it % 3) * STG3;
            #pragma unroll
            for (int i = 0; i < 4; i++) {
                int e = tid + 256 * i;
                int r = e >> 3, u = e & 7;
                uint32_t d = buf + (uint32_t)(r * 128 + ((u ^ (r & 7)) << 4));
                size_t so = (size_t)(m0 + r) * K + k0 + u * 8;
                cp16(d, Ahi + so);
                cp16(d + 16384, Alo + so);
            }
            #pragma unroll
            for (int i = 0; i < 4; i++) {
                int e = tid + 256 * i;
                int kr = e >> 4, u = e & 15;
                uint32_t d = buf + 32768 + (uint32_t)(kr * 256 + ((u ^ (kr & 7)) << 4));
                size_t so = (size_t)(k0 + kr) * Nb + n0 + u * 8;
                cp16(d, Bhi + so);
                cp16(d + 16384, Blo + so);
            }
        }
        cp_commit();
    };

    auto COMPUTE = [&](int stg) {
        uint32_t aBase = sb + stg * STG3;
        uint32_t bBase = aBase + 32768;
        #pragma unroll
        for (int ks = 0; ks < 4; ks++) {
            uint32_t ah[4][4], alr[4][4];
            #pragma unroll
            for (int mt = 0; mt < 4; mt++) {
                int r = wm * 64 + mt * 16 + (lane & 15);
                int c = ks * 2 + (lane >> 4);
                uint32_t off = (uint32_t)(r * 128 + ((c ^ (r & 7)) << 4));
                ldsm_x4(ah[mt],  aBase + off);
                ldsm_x4(alr[mt], aBase + 16384 + off);
            }
            uint32_t bh[4][2], blr[4][2];
            #pragma unroll
            for (int nt = 0; nt < 4; nt++) {
                int kt = ks * 16 + (lane & 15);
                int c = wn * 4 + nt;
                uint32_t off = (uint32_t)(kt * 256 + ((c ^ (kt & 7)) << 4));
                ldsm_x2t(bh[nt],  bBase + off);
                ldsm_x2t(blr[nt], bBase + 16384 + off);
            }
            #pragma unroll
            for (int mt = 0; mt < 4; mt++)
                #pragma unroll
                for (int nt = 0; nt < 4; nt++) {
                    mma_bf16(acc[mt][nt], ah[mt],  bh[nt]);
                    mma_bf16(acc[mt][nt], ah[mt],  blr[nt]);
                    mma_bf16(acc[mt][nt], alr[mt], bh[nt]);
                }
        }
    };

    PREFETCH(0);
    PREFETCH(1);
    for (int it = 0; it < niter; it++) {
        asm volatile("cp.async.wait_group 1;" ::: "memory");
        __syncthreads();
        COMPUTE(it % 3);
        PREFETCH(it + 2);
    }

    // epilogue
    #pragma unroll
    for (int mt = 0; mt < 4; mt++) {
        int r0 = m0 + wm * 64 + mt * 16 + (lane >> 2);
        #pragma unroll
        for (int nt = 0; nt < 4; nt++) {
            int c0 = n0 + wn * 32 + nt * 8 + (lane & 3) * 2;
            float v[4];
            #pragma unroll
            for (int i = 0; i < 4; i++) {
                v[i] = acc[mt][nt][i];
                int col = c0 + (i & 1);
                if (HAS_BIAS && col < Nc) v[i] += bias[col];
                if (DO_GELU) v[i] = gelu_exact(v[i]);
            }
            if (WRITE_PLANES) {
                #pragma unroll
                for (int half = 0; half < 2; half++) {
                    int row = r0 + half * 8;
                    __nv_bfloat16 h0, l0, h1, l1;
                    split1(v[half * 2],     h0, l0);
                    split1(v[half * 2 + 1], h1, l1);
                    size_t o = (size_t)row * Nc + c0;
                    *(__nv_bfloat162*)(Chi + o) = __halves2bfloat162(h0, h1);
                    *(__nv_bfloat162*)(Clo + o) = __halves2bfloat162(l0, l1);
                }
            } else {
                #pragma unroll
                for (int i = 0; i < 4; i++) {
                    int row = r0 + (i >> 1) * 8;
                    int col = c0 + (i & 1);
                    if (col < Nc) {
                        float w = v[i];
                        if (DO_RES) w += res[(size_t)row * Nc + col];
                        Cf[(size_t)row * Nc + col] = w;
                    }
                }
            }
        }
    }
}

// ================= 2-term fp16 GEMM (head): C = A*(Bh+Bl) =================
// Stage (48KB): A @0 (16KB), Bh @16384, Bl @32768. 3 stages = 144KB.

#define STG2 49152

__global__ __launch_bounds__(256, 1) void tc_gemm_head(
        const __half* __restrict__ Af,
        const __half* __restrict__ Bhi, const __half* __restrict__ Blo,
        float* __restrict__ Cf, int M, int Nb, int Nc, int K) {
    extern __shared__ __align__(1024) char dsm[];
    uint32_t sb = smem_u32(dsm);
    const int tid = threadIdx.x, lane = tid & 31, wid = tid >> 5;
    const int wm = wid >> 2, wn = wid & 3;
    const int m0 = blockIdx.x * 128, n0 = blockIdx.y * 128;
    const int niter = K >> 6;

    float acc[4][4][4];
    #pragma unroll
    for (int a = 0; a < 4; a++)
        #pragma unroll
        for (int b = 0; b < 4; b++)
            #pragma unroll
            for (int c = 0; c < 4; c++) acc[a][b][c] = 0.0f;

    auto PREFETCH = [&](int it) {
        if (it < niter) {
            int k0 = it << 6;
            uint32_t buf = sb + (it % 3) * STG2;
            #pragma unroll
            for (int i = 0; i < 4; i++) {
                int e = tid + 256 * i;
                int r = e >> 3, u = e & 7;
                uint32_t d = buf + (uint32_t)(r * 128 + ((u ^ (r & 7)) << 4));
                cp16(d, Af + (size_t)(m0 + r) * K + k0 + u * 8);
            }
            #pragma unroll
            for (int i = 0; i < 4; i++) {
                int e = tid + 256 * i;
                int kr = e >> 4, u = e & 15;
                uint32_t d = buf + 16384 + (uint32_t)(kr * 256 + ((u ^ (kr & 7)) << 4));
                size_t so = (size_t)(k0 + kr) * Nb + n0 + u * 8;
                cp16(d, Bhi + so);
                cp16(d + 16384, Blo + so);
            }
        }
        cp_commit();
    };

    auto COMPUTE = [&](int stg) {
        uint32_t aBase = sb + stg * STG2;
        uint32_t bBase = aBase + 16384;
        #pragma unroll
        for (int ks = 0; ks < 4; ks++) {
            uint32_t af[4][4];
            #pragma unroll
            for (int mt = 0; mt < 4; mt++) {
                int r = wm * 64 + mt * 16 + (lane & 15);
                int c = ks * 2 + (lane >> 4);
                uint32_t off = (uint32_t)(r * 128 + ((c ^ (r & 7)) << 4));
                ldsm_x4(af[mt], aBase + off);
            }
            uint32_t bh[4][2], blr[4][2];
            #pragma unroll
            for (int nt = 0; nt < 4; nt++) {
                int kt = ks * 16 + (lane & 15);
                int c = wn * 4 + nt;
                uint32_t off = (uint32_t)(kt * 256 + ((c ^ (kt & 7)) << 4));
                ldsm_x2t(bh[nt],  bBase + off);
                ldsm_x2t(blr[nt], bBase + 16384 + off);
            }
            #pragma unroll
            for (int mt = 0; mt < 4; mt++)
                #pragma unroll
                for (int nt = 0; nt < 4; nt++) {
                    mma_f16(acc[mt][nt], af[mt], bh[nt]);
                    mma_f16(acc[mt][nt], af[mt], blr[nt]);
                }
        }
    };

    PREFETCH(0);
    PREFETCH(1);
    for (int it = 0; it < niter; it++) {
        asm volatile("cp.async.wait_group 1;" ::: "memory");
        __syncthreads();
        COMPUTE(it % 3);
        PREFETCH(it + 2);
    }

    #pragma unroll
    for (int mt = 0; mt < 4; mt++) {
        int r0 = m0 + wm * 64 + mt * 16 + (lane >> 2);
        #pragma unroll
        for (int nt = 0; nt < 4; nt++) {
            int c0 = n0 + wn * 32 + nt * 8 + (lane & 3) * 2;
            #pragma unroll
            for (int i = 0; i < 4; i++) {
                int row = r0 + (i >> 1) * 8;
                int col = c0 + (i & 1);
                if (col < Nc)
                    Cf[(size_t)row * Nc + col] = acc[mt][nt][i];
            }
        }
    }
}

// ---------------- launch ----------------
extern "C" void kernel_launch(void* const* d_in, const int* in_sizes, int n_in,
                              void* d_out, int out_size) {
    const int*   idx    = (const int*)  d_in[0];
    const float* wte    = (const float*)d_in[1];
    const float* pte    = (const float*)d_in[2];
    const float* ln1_s  = (const float*)d_in[3];
    const float* ln1_b  = (const float*)d_in[4];
    const float* qkv_w  = (const float*)d_in[5];
    const float* qkv_b  = (const float*)d_in[6];
    const float* proj_w = (const float*)d_in[7];
    const float* proj_b = (const float*)d_in[8];
    const float* ln2_s  = (const float*)d_in[9];
    const float* ln2_b  = (const float*)d_in[10];
    const float* w1     = (const float*)d_in[11];
    const float* b1     = (const float*)d_in[12];
    const float* w2     = (const float*)d_in[13];
    const float* b2     = (const float*)d_in[14];
    const float* lnf_s  = (const float*)d_in[15];
    const float* lnf_b  = (const float*)d_in[16];
    const float* head_w = (const float*)d_in[17];
    float* out = (float*)d_out;

    float *px, *pqkv;
    cudaGetSymbolAddress((void**)&px,   g_x);
    cudaGetSymbolAddress((void**)&pqkv, g_qkv);
    __nv_bfloat16 *lnh, *lnl, *ath, *atl, *mdh, *mdl;
    cudaGetSymbolAddress((void**)&lnh, g_ln_h);  cudaGetSymbolAddress((void**)&lnl, g_ln_l);
    cudaGetSymbolAddress((void**)&ath, g_att_h); cudaGetSymbolAddress((void**)&atl, g_att_l);
    cudaGetSymbolAddress((void**)&mdh, g_mid_h); cudaGetSymbolAddress((void**)&mdl, g_mid_l);
    __half *lnf16, *hwh, *hwl;
    cudaGetSymbolAddress((void**)&lnf16, g_lnf16);
    cudaGetSymbolAddress((void**)&hwh, g_hw_h);  cudaGetSymbolAddress((void**)&hwl, g_hw_l);
    __nv_bfloat16 *qwh, *qwl, *pwh, *pwl, *w1h, *w1l, *w2h, *w2l;
    cudaGetSymbolAddress((void**)&qwh, g_qkvw_h); cudaGetSymbolAddress((void**)&qwl, g_qkvw_l);
    cudaGetSymbolAddress((void**)&pwh, g_projw_h); cudaGetSymbolAddress((void**)&pwl, g_projw_l);
    cudaGetSymbolAddress((void**)&w1h, g_w1_h);   cudaGetSymbolAddress((void**)&w1l, g_w1_l);
    cudaGetSymbolAddress((void**)&w2h, g_w2_h);   cudaGetSymbolAddress((void**)&w2l, g_w2_l);

    cudaFuncSetAttribute(tc_gemm<1,0,0,0>, cudaFuncAttributeMaxDynamicSharedMemorySize, 3 * STG3);
    cudaFuncSetAttribute(tc_gemm<1,0,1,0>, cudaFuncAttributeMaxDynamicSharedMemorySize, 3 * STG3);
    cudaFuncSetAttribute(tc_gemm<1,1,0,1>, cudaFuncAttributeMaxDynamicSharedMemorySize, 3 * STG3);
    cudaFuncSetAttribute(tc_gemm_head, cudaFuncAttributeMaxDynamicSharedMemorySize, 3 * STG2);

    // ---- weight conversion (once per replay) ----
    {
        int n;
        n = L_ * C_ * 3 * C_ / 4;
        convert_kernel<<<(n + 255) / 256, 256>>>(qkv_w, qwh, qwl, n);
        n = L_ * C_ * C_ / 4;
        convert_kernel<<<(n + 255) / 256, 256>>>(proj_w, pwh, pwl, n);
        n = L_ * C_ * F_ / 4;
        convert_kernel<<<(n + 255) / 256, 256>>>(w1, w1h, w1l, n);
        n = L_ * F_ * C_ / 4;
        convert_kernel<<<(n + 255) / 256, 256>>>(w2, w2h, w2l, n);
        n = C_ * VP_ / 4;
        convert_head_kernel<<<(n + 255) / 256, 256>>>(head_w, hwh, hwl);
    }

    embed_kernel<<<M_, 256>>>(idx, wte, pte, px);

    for (int l = 0; l < L_; l++) {
        const __nv_bfloat16* qwh_l = qwh + (size_t)l * C_ * 3 * C_;
        const __nv_bfloat16* qwl_l = qwl + (size_t)l * C_ * 3 * C_;
        const __nv_bfloat16* pwh_l = pwh + (size_t)l * C_ * C_;
        const __nv_bfloat16* pwl_l = pwl + (size_t)l * C_ * C_;
        const __nv_bfloat16* w1h_l = w1h + (size_t)l * C_ * F_;
        const __nv_bfloat16* w1l_l = w1l + (size_t)l * C_ * F_;
        const __nv_bfloat16* w2h_l = w2h + (size_t)l * F_ * C_;
        const __nv_bfloat16* w2l_l = w2l + (size_t)l * F_ * C_;

        layernorm_kernel<<<M_, 256>>>(px, ln1_s + (size_t)l * C_, ln1_b + (size_t)l * C_, lnh, lnl);

        tc_gemm<1,0,0,0><<<dim3(M_ / 128, 3 * C_ / 128), 256, 3 * STG3>>>(
            lnh, lnl, qwh_l, qwl_l, qkv_b + (size_t)l * 3 * C_, nullptr,
            pqkv, nullptr, nullptr, M_, 3 * C_, 3 * C_, C_);

        attn_kernel<<<dim3(T_ / 4, B_ * H_), dim3(32, 4)>>>(pqkv, ath, atl);

        tc_gemm<1,0,1,0><<<dim3(M_ / 128, C_ / 128), 256, 3 * STG3>>>(
            ath, atl, pwh_l, pwl_l, proj_b + (size_t)l * C_, px,
            px, nullptr, nullptr, M_, C_, C_, C_);

        layernorm_kernel<<<M_, 256>>>(px, ln2_s + (size_t)l * C_, ln2_b + (size_t)l * C_, lnh, lnl);

        tc_gemm<1,1,0,1><<<dim3(M_ / 128, F_ / 128), 256, 3 * STG3>>>(
            lnh, lnl, w1h_l, w1l_l, b1 + (size_t)l * F_, nullptr,
            nullptr, mdh, mdl, M_, F_, F_, C_);

        tc_gemm<1,0,1,0><<<dim3(M_ / 128, C_ / 128), 256, 3 * STG3>>>(
            mdh, mdl, w2h_l, w2l_l, b2 + (size_t)l * C_, px,
            px, nullptr, nullptr, M_, C_, C_, F_);
    }

    layernorm_f16_kernel<<<M_, 256>>>(px, lnf_s, lnf_b, lnf16);

    // logits = lnf @ head_w   [2048 x 50257], fp16 2-term, N padded to 50304
    tc_gemm_head<<<dim3(M_ / 128, VP_ / 128), 256, 3 * STG2>>>(
        lnf16, hwh, hwl, out, M_, VP_, V_, C_);
}

// round 7
// speedup vs baseline: 3.2833x; 1.0809x over previous
#include <cuda_runtime.h>
#include <cuda_fp16.h>
#include <math.h>
#include <stdint.h>

// ---------------- problem constants ----------------
#define L_  6
#define B_  2
#define T_  1024
#define C_  768
#define H_  12
#define D_  64
#define F_  3072
#define V_  50257
#define VP_ 50304              // V padded to /128
#define M_  (B_ * T_)          // 2048 rows
#define EPS_ 1e-5f

// ---------------- scratch (device globals, no runtime alloc) ----------------
__device__ float g_x  [M_ * C_];        // residual stream (fp32)
__device__ float g_qkv[M_ * 3 * C_];    // qkv (fp32, attn input)

// single-plane fp16 activations
__device__ __half g_ln16 [M_ * C_];
__device__ __half g_att16[M_ * C_];
__device__ __half g_mid16[M_ * F_];

// weight planes (fp16 hi/lo), converted once per replay
__device__ __half g_qkvw_h[L_ * C_ * 3 * C_], g_qkvw_l[L_ * C_ * 3 * C_];
__device__ __half g_projw_h[L_ * C_ * C_],    g_projw_l[L_ * C_ * C_];
__device__ __half g_w1_h  [L_ * C_ * F_],     g_w1_l  [L_ * C_ * F_];
__device__ __half g_w2_h  [L_ * F_ * C_],     g_w2_l  [L_ * F_ * C_];
__device__ __half g_hw_h  [C_ * VP_],         g_hw_l  [C_ * VP_];

// ---------------- helpers ----------------
__device__ __forceinline__ uint32_t smem_u32(const void* p) {
    uint32_t a;
    asm("{ .reg .u64 t; cvta.to.shared.u64 t, %1; cvt.u32.u64 %0, t; }" : "=r"(a) : "l"(p));
    return a;
}
__device__ __forceinline__ void cp16(uint32_t dst, const void* src) {
    asm volatile("cp.async.cg.shared.global [%0], [%1], 16;" :: "r"(dst), "l"(src));
}
__device__ __forceinline__ void cp_commit() {
    asm volatile("cp.async.commit_group;" ::: "memory");
}
__device__ __forceinline__ void ldsm_x4(uint32_t* r, uint32_t a) {
    asm volatile("ldmatrix.sync.aligned.m8n8.x4.shared.b16 {%0,%1,%2,%3}, [%4];"
        : "=r"(r[0]), "=r"(r[1]), "=r"(r[2]), "=r"(r[3]) : "r"(a));
}
__device__ __forceinline__ void ldsm_x2t(uint32_t* r, uint32_t a) {
    asm volatile("ldmatrix.sync.aligned.m8n8.x2.trans.shared.b16 {%0,%1}, [%2];"
        : "=r"(r[0]), "=r"(r[1]) : "r"(a));
}
__device__ __forceinline__ void mma_f16(float* d, const uint32_t* a, const uint32_t* b) {
    asm volatile("mma.sync.aligned.m16n8k16.row.col.f32.f16.f16.f32 "
        "{%0,%1,%2,%3}, {%4,%5,%6,%7}, {%8,%9}, {%0,%1,%2,%3};"
        : "+f"(d[0]), "+f"(d[1]), "+f"(d[2]), "+f"(d[3])
        : "r"(a[0]), "r"(a[1]), "r"(a[2]), "r"(a[3]), "r"(b[0]), "r"(b[1]));
}
__device__ __forceinline__ void split1h(float x, __half& h, __half& l) {
    h = __float2half_rn(x);
    l = __float2half_rn(x - __half2float(h));
}
__device__ __forceinline__ float gelu_exact(float v) {
    return 0.5f * v * (1.0f + erff(v * 0.70710678118654752f));
}

// ---------------- weight conversion (fp32 -> fp16 hi/lo) ----------------
__global__ void convert_kernel(const float* __restrict__ src,
                               __half* __restrict__ hi,
                               __half* __restrict__ lo, int n4) {
    int e = blockIdx.x * blockDim.x + threadIdx.x;
    if (e >= n4) return;
    float4 v = *(const float4*)(src + (size_t)e * 4);
    __half h[4], l[4];
    split1h(v.x, h[0], l[0]); split1h(v.y, h[1], l[1]);
    split1h(v.z, h[2], l[2]); split1h(v.w, h[3], l[3]);
    *(__half2*)(hi + (size_t)e * 4)     = *(__half2*)&h[0];
    *(__half2*)(hi + (size_t)e * 4 + 2) = *(__half2*)&h[2];
    *(__half2*)(lo + (size_t)e * 4)     = *(__half2*)&l[0];
    *(__half2*)(lo + (size_t)e * 4 + 2) = *(__half2*)&l[2];
}

// head_w [C_ x V_] -> padded fp16 planes [C_ x VP_]
__global__ void convert_head_kernel(const float* __restrict__ src,
                                    __half* __restrict__ hi,
                                    __half* __restrict__ lo) {
    int e = blockIdx.x * blockDim.x + threadIdx.x;
    if (e >= C_ * (VP_ / 4)) return;
    int row = e / (VP_ / 4);
    int c0  = (e % (VP_ / 4)) * 4;
    __half h[4], l[4];
    #pragma unroll
    for (int j = 0; j < 4; j++) {
        int c = c0 + j;
        float v = (c < V_) ? src[(size_t)row * V_ + c] : 0.0f;
        split1h(v, h[j], l[j]);
    }
    size_t o = (size_t)row * VP_ + c0;
    *(__half2*)(hi + o)     = *(__half2*)&h[0];
    *(__half2*)(hi + o + 2) = *(__half2*)&h[2];
    *(__half2*)(lo + o)     = *(__half2*)&l[0];
    *(__half2*)(lo + o + 2) = *(__half2*)&l[2];
}

// ---------------- embedding ----------------
__global__ void embed_kernel(const int* __restrict__ idx,
                             const float* __restrict__ wte,
                             const float* __restrict__ pte,
                             float* __restrict__ x) {
    int r = blockIdx.x;
    int t = r % T_;
    int tok = idx[r];
    const float* wrow = wte + (size_t)tok * C_;
    const float* prow = pte + (size_t)t * C_;
    float* xr = x + (size_t)r * C_;
    for (int c = threadIdx.x; c < C_; c += blockDim.x)
        xr[c] = wrow[c] + prow[c];
}

// ---------------- layernorm -> single fp16 plane ----------------
__global__ void layernorm_kernel(const float* __restrict__ x,
                                 const float* __restrict__ sc,
                                 const float* __restrict__ bi,
                                 __half* __restrict__ y) {
    __shared__ float sh1[256];
    __shared__ float sh2[256];
    int r = blockIdx.x;
    int tid = threadIdx.x;
    const float* xr = x + (size_t)r * C_;
    float v0 = xr[tid], v1 = xr[tid + 256], v2 = xr[tid + 512];
    float s  = v0 + v1 + v2;
    float ss = v0 * v0 + v1 * v1 + v2 * v2;
    sh1[tid] = s; sh2[tid] = ss;
    __syncthreads();
    for (int off = 128; off > 0; off >>= 1) {
        if (tid < off) { sh1[tid] += sh1[tid + off]; sh2[tid] += sh2[tid + off]; }
        __syncthreads();
    }
    float mu  = sh1[0] * (1.0f / C_);
    float var = sh2[0] * (1.0f / C_) - mu * mu;
    float rstd = rsqrtf(var + EPS_);
    size_t base = (size_t)r * C_;
    #pragma unroll
    for (int q = 0; q < 3; q++) {
        int c = tid + q * 256;
        float v = (q == 0 ? v0 : (q == 1 ? v1 : v2));
        y[base + c] = __float2half_rn((v - mu) * rstd * sc[c] + bi[c]);
    }
}

// ---------------- attention (4 keys/iter, float2 lanes) -> fp16 plane ----------------
__global__ void attn_kernel(const float* __restrict__ qkv,
                            __half* __restrict__ o16) {
    int lane = threadIdx.x;
    int q = blockIdx.x * blockDim.y + threadIdx.y;
    int bh = blockIdx.y;
    int b = bh / H_, h = bh % H_;

    const float* base = qkv + (size_t)b * T_ * 3 * C_;
    float2 q2 = *(const float2*)(base + (size_t)q * 3 * C_ + h * D_ + 2 * lane);
    float q0 = q2.x * 0.125f, q1 = q2.y * 0.125f;

    float m = -3.0e38f, l = 0.0f, a0 = 0.0f, a1 = 0.0f;
    int j = 0;
    const float* kbase = base + C_ + h * D_ + 2 * lane;
    const float* vbase = base + 2 * C_ + h * D_ + 2 * lane;
    for (; j + 3 <= q; j += 4) {
        float s[4];
        #pragma unroll
        for (int u = 0; u < 4; u++) {
            float2 k2 = *(const float2*)(kbase + (size_t)(j + u) * 3 * C_);
            s[u] = q0 * k2.x + q1 * k2.y;
        }
        #pragma unroll
        for (int off = 16; off > 0; off >>= 1) {
            #pragma unroll
            for (int u = 0; u < 4; u++)
                s[u] += __shfl_xor_sync(0xffffffff, s[u], off);
        }
        float mn = fmaxf(fmaxf(s[0], s[1]), fmaxf(s[2], s[3]));
        mn = fmaxf(m, mn);
        float corr = __expf(m - mn);
        l *= corr; a0 *= corr; a1 *= corr;
        #pragma unroll
        for (int u = 0; u < 4; u++) {
            float p = __expf(s[u] - mn);
            float2 v2 = *(const float2*)(vbase + (size_t)(j + u) * 3 * C_);
            l  += p;
            a0 += p * v2.x;
            a1 += p * v2.y;
        }
        m = mn;
    }
    for (; j <= q; j++) {
        float2 k2 = *(const float2*)(kbase + (size_t)j * 3 * C_);
        float s = q0 * k2.x + q1 * k2.y;
        #pragma unroll
        for (int off = 16; off > 0; off >>= 1)
            s += __shfl_xor_sync(0xffffffff, s, off);
        float mn = fmaxf(m, s);
        float corr = __expf(m - mn);
        float p = __expf(s - mn);
        float2 v2 = *(const float2*)(vbase + (size_t)j * 3 * C_);
        l  = l  * corr + p;
        a0 = a0 * corr + p * v2.x;
        a1 = a1 * corr + p * v2.y;
        m = mn;
    }
    float inv = 1.0f / l;
    size_t o = (size_t)(b * T_ + q) * C_ + h * D_ + 2 * lane;
    *(__half2*)(o16 + o) = __floats2half2_rn(a0 * inv, a1 * inv);
}

// ================= 2-term fp16 GEMM: C = A*(Bh+Bl), 3-stage cp.async =================
// Tile 128x128, BK=64, 256 threads.
// Stage (48KB): A[128x64] @0, Bh[64x128] @16384, Bl @32768. 3 stages = 144KB.

#define STG 49152

template<int HAS_BIAS, int DO_GELU, int DO_RES, int WRITE_F16>
__global__ __launch_bounds__(256, 1) void tc_gemm(
        const __half* __restrict__ Af,
        const __half* __restrict__ Bhi, const __half* __restrict__ Blo,
        const float* __restrict__ bias, const float* __restrict__ res,
        float* __restrict__ Cf, __half* __restrict__ C16,
        int M, int Nb, int Nc, int K) {
    extern __shared__ __align__(1024) char dsm[];
    uint32_t sb = smem_u32(dsm);
    const int tid = threadIdx.x, lane = tid & 31, wid = tid >> 5;
    const int wm = wid >> 2, wn = wid & 3;
    const int m0 = blockIdx.x * 128, n0 = blockIdx.y * 128;
    const int niter = K >> 6;

    float acc[4][4][4];
    #pragma unroll
    for (int a = 0; a < 4; a++)
        #pragma unroll
        for (int b = 0; b < 4; b++)
            #pragma unroll
            for (int c = 0; c < 4; c++) acc[a][b][c] = 0.0f;

    auto PREFETCH = [&](int it) {
        if (it < niter) {
            int k0 = it << 6;
            uint32_t buf = sb + (it % 3) * STG;
            #pragma unroll
            for (int i = 0; i < 4; i++) {
                int e = tid + 256 * i;
                int r = e >> 3, u = e & 7;
                uint32_t d = buf + (uint32_t)(r * 128 + ((u ^ (r & 7)) << 4));
                cp16(d, Af + (size_t)(m0 + r) * K + k0 + u * 8);
            }
            #pragma unroll
            for (int i = 0; i < 4; i++) {
                int e = tid + 256 * i;
                int kr = e >> 4, u = e & 15;
                uint32_t d = buf + 16384 + (uint32_t)(kr * 256 + ((u ^ (kr & 7)) << 4));
                size_t so = (size_t)(k0 + kr) * Nb + n0 + u * 8;
                cp16(d, Bhi + so);
                cp16(d + 16384, Blo + so);
            }
        }
        cp_commit();
    };

    auto COMPUTE = [&](int stg) {
        uint32_t aBase = sb + stg * STG;
        uint32_t bBase = aBase + 16384;
        #pragma unroll
        for (int ks = 0; ks < 4; ks++) {
            uint32_t af[4][4];
            #pragma unroll
            for (int mt = 0; mt < 4; mt++) {
                int r = wm * 64 + mt * 16 + (lane & 15);
                int c = ks * 2 + (lane >> 4);
                uint32_t off = (uint32_t)(r * 128 + ((c ^ (r & 7)) << 4));
                ldsm_x4(af[mt], aBase + off);
            }
            uint32_t bh[4][2], blr[4][2];
            #pragma unroll
            for (int nt = 0; nt < 4; nt++) {
                int kt = ks * 16 + (lane & 15);
                int c = wn * 4 + nt;
                uint32_t off = (uint32_t)(kt * 256 + ((c ^ (kt & 7)) << 4));
                ldsm_x2t(bh[nt],  bBase + off);
                ldsm_x2t(blr[nt], bBase + 16384 + off);
            }
            #pragma unroll
            for (int mt = 0; mt < 4; mt++)
                #pragma unroll
                for (int nt = 0; nt < 4; nt++) {
                    mma_f16(acc[mt][nt], af[mt], bh[nt]);
                    mma_f16(acc[mt][nt], af[mt], blr[nt]);
                }
        }
    };

    PREFETCH(0);
    PREFETCH(1);
    for (int it = 0; it < niter; it++) {
        asm volatile("cp.async.wait_group 1;" ::: "memory");
        __syncthreads();
        COMPUTE(it % 3);
        PREFETCH(it + 2);
    }

    // epilogue
    #pragma unroll
    for (int mt = 0; mt < 4; mt++) {
        int r0 = m0 + wm * 64 + mt * 16 + (lane >> 2);
        #pragma unroll
        for (int nt = 0; nt < 4; nt++) {
            int c0 = n0 + wn * 32 + nt * 8 + (lane & 3) * 2;
            float v[4];
            #pragma unroll
            for (int i = 0; i < 4; i++) {
                v[i] = acc[mt][nt][i];
                int col = c0 + (i & 1);
                if (HAS_BIAS && col < Nc) v[i] += bias[col];
                if (DO_GELU) v[i] = gelu_exact(v[i]);
            }
            if (WRITE_F16) {
                #pragma unroll
                for (int half_i = 0; half_i < 2; half_i++) {
                    int row = r0 + half_i * 8;
                    size_t o = (size_t)row * Nc + c0;
                    *(__half2*)(C16 + o) =
                        __floats2half2_rn(v[half_i * 2], v[half_i * 2 + 1]);
                }
            } else {
                #pragma unroll
                for (int i = 0; i < 4; i++) {
                    int row = r0 + (i >> 1) * 8;
                    int col = c0 + (i & 1);
                    if (col < Nc) {
                        float w = v[i];
                        if (DO_RES) w += res[(size_t)row * Nc + col];
                        Cf[(size_t)row * Nc + col] = w;
                    }
                }
            }
        }
    }
}

// ---------------- launch ----------------
extern "C" void kernel_launch(void* const* d_in, const int* in_sizes, int n_in,
                              void* d_out, int out_size) {
    const int*   idx    = (const int*)  d_in[0];
    const float* wte    = (const float*)d_in[1];
    const float* pte    = (const float*)d_in[2];
    const float* ln1_s  = (const float*)d_in[3];
    const float* ln1_b  = (const float*)d_in[4];
    const float* qkv_w  = (const float*)d_in[5];
    const float* qkv_b  = (const float*)d_in[6];
    const float* proj_w = (const float*)d_in[7];
    const float* proj_b = (const float*)d_in[8];
    const float* ln2_s  = (const float*)d_in[9];
    const float* ln2_b  = (const float*)d_in[10];
    const float* w1     = (const float*)d_in[11];
    const float* b1     = (const float*)d_in[12];
    const float* w2     = (const float*)d_in[13];
    const float* b2     = (const float*)d_in[14];
    const float* lnf_s  = (const float*)d_in[15];
    const float* lnf_b  = (const float*)d_in[16];
    const float* head_w = (const float*)d_in[17];
    float* out = (float*)d_out;

    float *px, *pqkv;
    cudaGetSymbolAddress((void**)&px,   g_x);
    cudaGetSymbolAddress((void**)&pqkv, g_qkv);
    __half *ln16, *att16, *mid16;
    cudaGetSymbolAddress((void**)&ln16,  g_ln16);
    cudaGetSymbolAddress((void**)&att16, g_att16);
    cudaGetSymbolAddress((void**)&mid16, g_mid16);
    __half *qwh, *qwl, *pwh, *pwl, *w1h, *w1l, *w2h, *w2l, *hwh, *hwl;
    cudaGetSymbolAddress((void**)&qwh, g_qkvw_h); cudaGetSymbolAddress((void**)&qwl, g_qkvw_l);
    cudaGetSymbolAddress((void**)&pwh, g_projw_h); cudaGetSymbolAddress((void**)&pwl, g_projw_l);
    cudaGetSymbolAddress((void**)&w1h, g_w1_h);   cudaGetSymbolAddress((void**)&w1l, g_w1_l);
    cudaGetSymbolAddress((void**)&w2h, g_w2_h);   cudaGetSymbolAddress((void**)&w2l, g_w2_l);
    cudaGetSymbolAddress((void**)&hwh, g_hw_h);   cudaGetSymbolAddress((void**)&hwl, g_hw_l);

    cudaFuncSetAttribute(tc_gemm<1,0,0,0>, cudaFuncAttributeMaxDynamicSharedMemorySize, 3 * STG);
    cudaFuncSetAttribute(tc_gemm<1,0,1,0>, cudaFuncAttributeMaxDynamicSharedMemorySize, 3 * STG);
    cudaFuncSetAttribute(tc_gemm<1,1,0,1>, cudaFuncAttributeMaxDynamicSharedMemorySize, 3 * STG);
    cudaFuncSetAttribute(tc_gemm<0,0,0,0>, cudaFuncAttributeMaxDynamicSharedMemorySize, 3 * STG);

    // ---- weight conversion (once per replay) ----
    {
        int n;
        n = L_ * C_ * 3 * C_ / 4;
        convert_kernel<<<(n + 255) / 256, 256>>>(qkv_w, qwh, qwl, n);
        n = L_ * C_ * C_ / 4;
        convert_kernel<<<(n + 255) / 256, 256>>>(proj_w, pwh, pwl, n);
        n = L_ * C_ * F_ / 4;
        convert_kernel<<<(n + 255) / 256, 256>>>(w1, w1h, w1l, n);
        n = L_ * F_ * C_ / 4;
        convert_kernel<<<(n + 255) / 256, 256>>>(w2, w2h, w2l, n);
        n = C_ * VP_ / 4;
        convert_head_kernel<<<(n + 255) / 256, 256>>>(head_w, hwh, hwl);
    }

    embed_kernel<<<M_, 256>>>(idx, wte, pte, px);

    for (int l = 0; l < L_; l++) {
        const __half* qwh_l = qwh + (size_t)l * C_ * 3 * C_;
        const __half* qwl_l = qwl + (size_t)l * C_ * 3 * C_;
        const __half* pwh_l = pwh + (size_t)l * C_ * C_;
        const __half* pwl_l = pwl + (size_t)l * C_ * C_;
        const __half* w1h_l = w1h + (size_t)l * C_ * F_;
        const __half* w1l_l = w1l + (size_t)l * C_ * F_;
        const __half* w2h_l = w2h + (size_t)l * F_ * C_;
        const __half* w2l_l = w2l + (size_t)l * F_ * C_;

        layernorm_kernel<<<M_, 256>>>(px, ln1_s + (size_t)l * C_, ln1_b + (size_t)l * C_, ln16);

        // qkv = ln @ qkv_w + qkv_b  -> fp32
        tc_gemm<1,0,0,0><<<dim3(M_ / 128, 3 * C_ / 128), 256, 3 * STG>>>(
            ln16, qwh_l, qwl_l, qkv_b + (size_t)l * 3 * C_, nullptr,
            pqkv, nullptr, M_, 3 * C_, 3 * C_, C_);

        attn_kernel<<<dim3(T_ / 4, B_ * H_), dim3(32, 4)>>>(pqkv, att16);

        // x = x + att @ proj_w + proj_b
        tc_gemm<1,0,1,0><<<dim3(M_ / 128, C_ / 128), 256, 3 * STG>>>(
            att16, pwh_l, pwl_l, proj_b + (size_t)l * C_, px,
            px, nullptr, M_, C_, C_, C_);

        layernorm_kernel<<<M_, 256>>>(px, ln2_s + (size_t)l * C_, ln2_b + (size_t)l * C_, ln16);

        // mid = gelu(ln2 @ w1 + b1) -> fp16
        tc_gemm<1,1,0,1><<<dim3(M_ / 128, F_ / 128), 256, 3 * STG>>>(
            ln16, w1h_l, w1l_l, b1 + (size_t)l * F_, nullptr,
            nullptr, mid16, M_, F_, F_, C_);

        // x = x + mid @ w2 + b2
        tc_gemm<1,0,1,0><<<dim3(M_ / 128, C_ / 128), 256, 3 * STG>>>(
            mid16, w2h_l, w2l_l, b2 + (size_t)l * C_, px,
            px, nullptr, M_, C_, C_, F_);
    }

    layernorm_kernel<<<M_, 256>>>(px, lnf_s, lnf_b, ln16);

    // logits = lnf @ head_w   [2048 x 50257], N padded to 50304
    tc_gemm<0,0,0,0><<<dim3(M_ / 128, VP_ / 128), 256, 3 * STG>>>(
        ln16, hwh, hwl, nullptr, nullptr,
        out, nullptr, M_, VP_, V_, C_);
}

// round 8
// speedup vs baseline: 7.1280x; 2.1710x over previous
#include <cuda_runtime.h>
#include <cuda_fp16.h>
#include <math.h>
#include <stdint.h>

// ---------------- problem constants ----------------
#define L_  6
#define B_  2
#define T_  1024
#define C_  768
#define H_  12
#define D_  64
#define F_  3072
#define V_  50257
#define VP_ 50304              // V padded to /128
#define M_  (B_ * T_)          // 2048 rows
#define EPS_ 1e-5f

// ---------------- scratch (device globals, no runtime alloc) ----------------
__device__ float g_x  [M_ * C_];        // residual stream (fp32)
__device__ float g_qkv[M_ * 3 * C_];    // qkv (fp32, attn input)

// single-plane fp16 activations
__device__ __half g_ln16 [M_ * C_];
__device__ __half g_att16[M_ * C_];
__device__ __half g_mid16[M_ * F_];

// weight planes (fp16 hi/lo), converted once per replay
__device__ __half g_qkvw_h[L_ * C_ * 3 * C_], g_qkvw_l[L_ * C_ * 3 * C_];
__device__ __half g_projw_h[L_ * C_ * C_],    g_projw_l[L_ * C_ * C_];
__device__ __half g_w1_h  [L_ * C_ * F_],     g_w1_l  [L_ * C_ * F_];
__device__ __half g_w2_h  [L_ * F_ * C_],     g_w2_l  [L_ * F_ * C_];
__device__ __half g_hw_h  [C_ * VP_],         g_hw_l  [C_ * VP_];

// ---------------- helpers ----------------
__device__ __forceinline__ uint32_t smem_u32(const void* p) {
    uint32_t a;
    asm("{ .reg .u64 t; cvta.to.shared.u64 t, %1; cvt.u32.u64 %0, t; }" : "=r"(a) : "l"(p));
    return a;
}
__device__ __forceinline__ void cp16(uint32_t dst, const void* src) {
    asm volatile("cp.async.cg.shared.global [%0], [%1], 16;" :: "r"(dst), "l"(src));
}
__device__ __forceinline__ void cp_commit() {
    asm volatile("cp.async.commit_group;" ::: "memory");
}
__device__ __forceinline__ void ldsm_x4(uint32_t* r, uint32_t a) {
    asm volatile("ldmatrix.sync.aligned.m8n8.x4.shared.b16 {%0,%1,%2,%3}, [%4];"
        : "=r"(r[0]), "=r"(r[1]), "=r"(r[2]), "=r"(r[3]) : "r"(a));
}
__device__ __forceinline__ void ldsm_x2(uint32_t* r, uint32_t a) {
    asm volatile("ldmatrix.sync.aligned.m8n8.x2.shared.b16 {%0,%1}, [%2];"
        : "=r"(r[0]), "=r"(r[1]) : "r"(a));
}
__device__ __forceinline__ void ldsm_x2t(uint32_t* r, uint32_t a) {
    asm volatile("ldmatrix.sync.aligned.m8n8.x2.trans.shared.b16 {%0,%1}, [%2];"
        : "=r"(r[0]), "=r"(r[1]) : "r"(a));
}
__device__ __forceinline__ void mma_f16(float* d, const uint32_t* a, const uint32_t* b) {
    asm volatile("mma.sync.aligned.m16n8k16.row.col.f32.f16.f16.f32 "
        "{%0,%1,%2,%3}, {%4,%5,%6,%7}, {%8,%9}, {%0,%1,%2,%3};"
        : "+f"(d[0]), "+f"(d[1]), "+f"(d[2]), "+f"(d[3])
        : "r"(a[0]), "r"(a[1]), "r"(a[2]), "r"(a[3]), "r"(b[0]), "r"(b[1]));
}
__device__ __forceinline__ uint32_t packh2(float a, float b) {
    __half2 t = __floats2half2_rn(a, b);
    return *(uint32_t*)&t;
}
__device__ __forceinline__ void split1h(float x, __half& h, __half& l) {
    h = __float2half_rn(x);
    l = __float2half_rn(x - __half2float(h));
}
__device__ __forceinline__ float gelu_exact(float v) {
    return 0.5f * v * (1.0f + erff(v * 0.70710678118654752f));
}

// ---------------- weight conversion (fp32 -> fp16 hi/lo) ----------------
__global__ void convert_kernel(const float* __restrict__ src,
                               __half* __restrict__ hi,
                               __half* __restrict__ lo, int n4) {
    int e = blockIdx.x * blockDim.x + threadIdx.x;
    if (e >= n4) return;
    float4 v = *(const float4*)(src + (size_t)e * 4);
    __half h[4], l[4];
    split1h(v.x, h[0], l[0]); split1h(v.y, h[1], l[1]);
    split1h(v.z, h[2], l[2]); split1h(v.w, h[3], l[3]);
    *(__half2*)(hi + (size_t)e * 4)     = *(__half2*)&h[0];
    *(__half2*)(hi + (size_t)e * 4 + 2) = *(__half2*)&h[2];
    *(__half2*)(lo + (size_t)e * 4)     = *(__half2*)&l[0];
    *(__half2*)(lo + (size_t)e * 4 + 2) = *(__half2*)&l[2];
}

// head_w [C_ x V_] -> padded fp16 planes [C_ x VP_]
__global__ void convert_head_kernel(const float* __restrict__ src,
                                    __half* __restrict__ hi,
                                    __half* __restrict__ lo) {
    int e = blockIdx.x * blockDim.x + threadIdx.x;
    if (e >= C_ * (VP_ / 4)) return;
    int row = e / (VP_ / 4);
    int c0  = (e % (VP_ / 4)) * 4;
    __half h[4], l[4];
    #pragma unroll
    for (int j = 0; j < 4; j++) {
        int c = c0 + j;
        float v = (c < V_) ? src[(size_t)row * V_ + c] : 0.0f;
        split1h(v, h[j], l[j]);
    }
    size_t o = (size_t)row * VP_ + c0;
    *(__half2*)(hi + o)     = *(__half2*)&h[0];
    *(__half2*)(hi + o + 2) = *(__half2*)&h[2];
    *(__half2*)(lo + o)     = *(__half2*)&l[0];
    *(__half2*)(lo + o + 2) = *(__half2*)&l[2];
}

// ---------------- embedding ----------------
__global__ void embed_kernel(const int* __restrict__ idx,
                             const float* __restrict__ wte,
                             const float* __restrict__ pte,
                             float* __restrict__ x) {
    int r = blockIdx.x;
    int t = r % T_;
    int tok = idx[r];
    const float* wrow = wte + (size_t)tok * C_;
    const float* prow = pte + (size_t)t * C_;
    float* xr = x + (size_t)r * C_;
    for (int c = threadIdx.x; c < C_; c += blockDim.x)
        xr[c] = wrow[c] + prow[c];
}

// ---------------- layernorm -> single fp16 plane ----------------
__global__ void layernorm_kernel(const float* __restrict__ x,
                                 const float* __restrict__ sc,
                                 const float* __restrict__ bi,
                                 __half* __restrict__ y) {
    __shared__ float sh1[256];
    __shared__ float sh2[256];
    int r = blockIdx.x;
    int tid = threadIdx.x;
    const float* xr = x + (size_t)r * C_;
    float v0 = xr[tid], v1 = xr[tid + 256], v2 = xr[tid + 512];
    float s  = v0 + v1 + v2;
    float ss = v0 * v0 + v1 * v1 + v2 * v2;
    sh1[tid] = s; sh2[tid] = ss;
    __syncthreads();
    for (int off = 128; off > 0; off >>= 1) {
        if (tid < off) { sh1[tid] += sh1[tid + off]; sh2[tid] += sh2[tid + off]; }
        __syncthreads();
    }
    float mu  = sh1[0] * (1.0f / C_);
    float var = sh2[0] * (1.0f / C_) - mu * mu;
    float rstd = rsqrtf(var + EPS_);
    size_t base = (size_t)r * C_;
    #pragma unroll
    for (int q = 0; q < 3; q++) {
        int c = tid + q * 256;
        float v = (q == 0 ? v0 : (q == 1 ? v1 : v2));
        y[base + c] = __float2half_rn((v - mu) * rstd * sc[c] + bi[c]);
    }
}

// ---------------- FA2-style block attention: 64q x 64k tiles, mma ----------------
// Grid (T/64, B*H). Block 128 threads (4 warps, each 16 q rows).
__global__ __launch_bounds__(128) void attn_kernel(const float* __restrict__ qkv,
                                                   __half* __restrict__ o16) {
    __shared__ __align__(1024) __half sQ[64 * 64];
    __shared__ __align__(1024) __half sK[64 * 64];
    __shared__ __align__(1024) __half sV[64 * 64];
    uint32_t qB = smem_u32(sQ), kB = smem_u32(sK), vB = smem_u32(sV);
    int tid = threadIdx.x, lane = tid & 31, wid = tid >> 5;
    int q0 = blockIdx.x * 64;
    int bh = blockIdx.y;
    int b = bh / H_, h = bh % H_;
    const float* base = qkv + (size_t)b * T_ * 3 * C_ + h * D_;

    // ---- load Q tile (scaled 1/8), fp16, swizzled ----
    #pragma unroll
    for (int i = 0; i < 8; i++) {
        int e = tid + 128 * i;          // 0..1023 8B-units
        int r = e >> 4, u = e & 15;
        const float* src = base + (size_t)(q0 + r) * 3 * C_ + u * 4;
        float2 a0 = *(const float2*)(src);
        float2 a1 = *(const float2*)(src + 2);
        uint32_t off = (uint32_t)(r * 128 + (((u >> 1) ^ (r & 7)) << 4) + (u & 1) * 8);
        *(__half2*)((char*)sQ + off)     = __floats2half2_rn(a0.x * 0.125f, a0.y * 0.125f);
        *(__half2*)((char*)sQ + off + 4) = __floats2half2_rn(a1.x * 0.125f, a1.y * 0.125f);
    }
    __syncthreads();

    // ---- Q fragments (once) ----
    uint32_t qa[4][4];
    #pragma unroll
    for (int ks = 0; ks < 4; ks++) {
        int r = wid * 16 + (lane & 15);
        int c = ks * 2 + (lane >> 4);
        ldsm_x4(qa[ks], qB + (uint32_t)(r * 128 + ((c ^ (r & 7)) << 4)));
    }

    float m1 = -1e30f, m2 = -1e30f, l1 = 0.0f, l2 = 0.0f;
    float oacc[8][4];
    #pragma unroll
    for (int dt = 0; dt < 8; dt++)
        #pragma unroll
        for (int i = 0; i < 4; i++) oacc[dt][i] = 0.0f;

    int r1loc = wid * 16 + (lane >> 2);     // local q row of c0/c1 regs

    for (int j0 = 0; j0 <= q0; j0 += 64) {
        __syncthreads();
        // ---- load K,V tiles fp32->fp16 swizzled ----
        #pragma unroll
        for (int i = 0; i < 8; i++) {
            int e = tid + 128 * i;
            int r = e >> 4, u = e & 15;
            const float* srck = base + C_ + (size_t)(j0 + r) * 3 * C_ + u * 4;
            const float* srcv = base + 2 * C_ + (size_t)(j0 + r) * 3 * C_ + u * 4;
            uint32_t off = (uint32_t)(r * 128 + (((u >> 1) ^ (r & 7)) << 4) + (u & 1) * 8);
            float2 k0 = *(const float2*)(srck);
            float2 k1 = *(const float2*)(srck + 2);
            *(__half2*)((char*)sK + off)     = __floats2half2_rn(k0.x, k0.y);
            *(__half2*)((char*)sK + off + 4) = __floats2half2_rn(k1.x, k1.y);
            float2 v0 = *(const float2*)(srcv);
            float2 v1 = *(const float2*)(srcv + 2);
            *(__half2*)((char*)sV + off)     = __floats2half2_rn(v0.x, v0.y);
            *(__half2*)((char*)sV + off + 4) = __floats2half2_rn(v1.x, v1.y);
        }
        __syncthreads();

        // ---- S = Q K^T ----
        float sc[8][4];
        #pragma unroll
        for (int nt = 0; nt < 8; nt++)
            #pragma unroll
            for (int i = 0; i < 4; i++) sc[nt][i] = 0.0f;
        #pragma unroll
        for (int ks = 0; ks < 4; ks++) {
            #pragma unroll
            for (int nt = 0; nt < 8; nt++) {
                int n = nt * 8 + (lane & 7);
                int g = ks * 2 + ((lane >> 3) & 1);
                uint32_t kb[2];
                ldsm_x2(kb, kB + (uint32_t)(n * 128 + ((g ^ (n & 7)) << 4)));
                mma_f16(sc[nt], qa[ks], kb);
            }
        }

        // ---- causal mask on diagonal tile ----
        if (j0 == q0) {
            #pragma unroll
            for (int nt = 0; nt < 8; nt++) {
                int cb = nt * 8 + (lane & 3) * 2;
                if (cb     > r1loc) sc[nt][0] = -1e30f;
                if (cb + 1 > r1loc) sc[nt][1] = -1e30f;
                if (cb     > r1loc + 8) sc[nt][2] = -1e30f;
                if (cb + 1 > r1loc + 8) sc[nt][3] = -1e30f;
            }
        }

        // ---- online softmax ----
        float nm1 = m1, nm2 = m2;
        #pragma unroll
        for (int nt = 0; nt < 8; nt++) {
            nm1 = fmaxf(nm1, fmaxf(sc[nt][0], sc[nt][1]));
            nm2 = fmaxf(nm2, fmaxf(sc[nt][2], sc[nt][3]));
        }
        #pragma unroll
        for (int o = 1; o <= 2; o <<= 1) {
            nm1 = fmaxf(nm1, __shfl_xor_sync(0xffffffff, nm1, o));
            nm2 = fmaxf(nm2, __shfl_xor_sync(0xffffffff, nm2, o));
        }
        float corr1 = __expf(m1 - nm1);
        float corr2 = __expf(m2 - nm2);
        m1 = nm1; m2 = nm2;
        float rs1 = 0.0f, rs2 = 0.0f;
        #pragma unroll
        for (int nt = 0; nt < 8; nt++) {
            sc[nt][0] = __expf(sc[nt][0] - m1);
            sc[nt][1] = __expf(sc[nt][1] - m1);
            sc[nt][2] = __expf(sc[nt][2] - m2);
            sc[nt][3] = __expf(sc[nt][3] - m2);
            rs1 += sc[nt][0] + sc[nt][1];
            rs2 += sc[nt][2] + sc[nt][3];
        }
        #pragma unroll
        for (int o = 1; o <= 2; o <<= 1) {
            rs1 += __shfl_xor_sync(0xffffffff, rs1, o);
            rs2 += __shfl_xor_sync(0xffffffff, rs2, o);
        }
        l1 = l1 * corr1 + rs1;
        l2 = l2 * corr2 + rs2;
        #pragma unroll
        for (int dt = 0; dt < 8; dt++) {
            oacc[dt][0] *= corr1; oacc[dt][1] *= corr1;
            oacc[dt][2] *= corr2; oacc[dt][3] *= corr2;
        }

        // ---- O += P V ----
        #pragma unroll
        for (int ks = 0; ks < 4; ks++) {
            uint32_t pa[4];
            pa[0] = packh2(sc[2 * ks][0],     sc[2 * ks][1]);
            pa[1] = packh2(sc[2 * ks][2],     sc[2 * ks][3]);
            pa[2] = packh2(sc[2 * ks + 1][0], sc[2 * ks + 1][1]);
            pa[3] = packh2(sc[2 * ks + 1][2], sc[2 * ks + 1][3]);
            #pragma unroll
            for (int dt = 0; dt < 8; dt++) {
                int kt = ks * 16 + (lane & 15);
                uint32_t vb[2];
                ldsm_x2t(vb, vB + (uint32_t)(kt * 128 + ((dt ^ (kt & 7)) << 4)));
                mma_f16(oacc[dt], pa, vb);
            }
        }
    }

    // ---- epilogue ----
    float inv1 = 1.0f / l1, inv2 = 1.0f / l2;
    int rowg = b * T_ + q0 + r1loc;
    #pragma unroll
    for (int dt = 0; dt < 8; dt++) {
        int col = h * D_ + dt * 8 + (lane & 3) * 2;
        *(__half2*)(o16 + (size_t)rowg * C_ + col) =
            __floats2half2_rn(oacc[dt][0] * inv1, oacc[dt][1] * inv1);
        *(__half2*)(o16 + (size_t)(rowg + 8) * C_ + col) =
            __floats2half2_rn(oacc[dt][2] * inv2, oacc[dt][3] * inv2);
    }
}

// ================= 2-term fp16 GEMM: C = A*(Bh+Bl), 3-stage cp.async =================
// Tile 128x128, BK=64, 256 threads.
// Stage (48KB): A[128x64] @0, Bh[64x128] @16384, Bl @32768. 3 stages = 144KB.

#define STG 49152

template<int HAS_BIAS, int DO_GELU, int DO_RES, int WRITE_F16>
__global__ __launch_bounds__(256, 1) void tc_gemm(
        const __half* __restrict__ Af,
        const __half* __restrict__ Bhi, const __half* __restrict__ Blo,
        const float* __restrict__ bias, const float* __restrict__ res,
        float* __restrict__ Cf, __half* __restrict__ C16,
        int M, int Nb, int Nc, int K) {
    extern __shared__ __align__(1024) char dsm[];
    uint32_t sb = smem_u32(dsm);
    const int tid = threadIdx.x, lane = tid & 31, wid = tid >> 5;
    const int wm = wid >> 2, wn = wid & 3;
    const int m0 = blockIdx.x * 128, n0 = blockIdx.y * 128;
    const int niter = K >> 6;

    float acc[4][4][4];
    #pragma unroll
    for (int a = 0; a < 4; a++)
        #pragma unroll
        for (int b = 0; b < 4; b++)
            #pragma unroll
            for (int c = 0; c < 4; c++) acc[a][b][c] = 0.0f;

    auto PREFETCH = [&](int it) {
        if (it < niter) {
            int k0 = it << 6;
            uint32_t buf = sb + (it % 3) * STG;
            #pragma unroll
            for (int i = 0; i < 4; i++) {
                int e = tid + 256 * i;
                int r = e >> 3, u = e & 7;
                uint32_t d = buf + (uint32_t)(r * 128 + ((u ^ (r & 7)) << 4));
                cp16(d, Af + (size_t)(m0 + r) * K + k0 + u * 8);
            }
            #pragma unroll
            for (int i = 0; i < 4; i++) {
                int e = tid + 256 * i;
                int kr = e >> 4, u = e & 15;
                uint32_t d = buf + 16384 + (uint32_t)(kr * 256 + ((u ^ (kr & 7)) << 4));
                size_t so = (size_t)(k0 + kr) * Nb + n0 + u * 8;
                cp16(d, Bhi + so);
                cp16(d + 16384, Blo + so);
            }
        }
        cp_commit();
    };

    auto COMPUTE = [&](int stg) {
        uint32_t aBase = sb + stg * STG;
        uint32_t bBase = aBase + 16384;
        #pragma unroll
        for (int ks = 0; ks < 4; ks++) {
            uint32_t af[4][4];
            #pragma unroll
            for (int mt = 0; mt < 4; mt++) {
                int r = wm * 64 + mt * 16 + (lane & 15);
                int c = ks * 2 + (lane >> 4);
                uint32_t off = (uint32_t)(r * 128 + ((c ^ (r & 7)) << 4));
                ldsm_x4(af[mt], aBase + off);
            }
            uint32_t bh[4][2], blr[4][2];
            #pragma unroll
            for (int nt = 0; nt < 4; nt++) {
                int kt = ks * 16 + (lane & 15);
                int c = wn * 4 + nt;
                uint32_t off = (uint32_t)(kt * 256 + ((c ^ (kt & 7)) << 4));
                ldsm_x2t(bh[nt],  bBase + off);
                ldsm_x2t(blr[nt], bBase + 16384 + off);
            }
            #pragma unroll
            for (int mt = 0; mt < 4; mt++)
                #pragma unroll
                for (int nt = 0; nt < 4; nt++) {
                    mma_f16(acc[mt][nt], af[mt], bh[nt]);
                    mma_f16(acc[mt][nt], af[mt], blr[nt]);
                }
        }
    };

    PREFETCH(0);
    PREFETCH(1);
    for (int it = 0; it < niter; it++) {
        asm volatile("cp.async.wait_group 1;" ::: "memory");
        __syncthreads();
        COMPUTE(it % 3);
        PREFETCH(it + 2);
    }

    // epilogue
    #pragma unroll
    for (int mt = 0; mt < 4; mt++) {
        int r0 = m0 + wm * 64 + mt * 16 + (lane >> 2);
        #pragma unroll
        for (int nt = 0; nt < 4; nt++) {
            int c0 = n0 + wn * 32 + nt * 8 + (lane & 3) * 2;
            float v[4];
            #pragma unroll
            for (int i = 0; i < 4; i++) {
                v[i] = acc[mt][nt][i];
                int col = c0 + (i & 1);
                if (HAS_BIAS && col < Nc) v[i] += bias[col];
                if (DO_GELU) v[i] = gelu_exact(v[i]);
            }
            if (WRITE_F16) {
                #pragma unroll
                for (int half_i = 0; half_i < 2; half_i++) {
                    int row = r0 + half_i * 8;
                    size_t o = (size_t)row * Nc + c0;
                    *(__half2*)(C16 + o) =
                        __floats2half2_rn(v[half_i * 2], v[half_i * 2 + 1]);
                }
            } else {
                #pragma unroll
                for (int i = 0; i < 4; i++) {
                    int row = r0 + (i >> 1) * 8;
                    int col = c0 + (i & 1);
                    if (col < Nc) {
                        float w = v[i];
                        if (DO_RES) w += res[(size_t)row * Nc + col];
                        Cf[(size_t)row * Nc + col] = w;
                    }
                }
            }
        }
    }
}

// ---------------- launch ----------------
extern "C" void kernel_launch(void* const* d_in, const int* in_sizes, int n_in,
                              void* d_out, int out_size) {
    const int*   idx    = (const int*)  d_in[0];
    const float* wte    = (const float*)d_in[1];
    const float* pte    = (const float*)d_in[2];
    const float* ln1_s  = (const float*)d_in[3];
    const float* ln1_b  = (const float*)d_in[4];
    const float* qkv_w  = (const float*)d_in[5];
    const float* qkv_b  = (const float*)d_in[6];
    const float* proj_w = (const float*)d_in[7];
    const float* proj_b = (const float*)d_in[8];
    const float* ln2_s  = (const float*)d_in[9];
    const float* ln2_b  = (const float*)d_in[10];
    const float* w1     = (const float*)d_in[11];
    const float* b1     = (const float*)d_in[12];
    const float* w2     = (const float*)d_in[13];
    const float* b2     = (const float*)d_in[14];
    const float* lnf_s  = (const float*)d_in[15];
    const float* lnf_b  = (const float*)d_in[16];
    const float* head_w = (const float*)d_in[17];
    float* out = (float*)d_out;

    float *px, *pqkv;
    cudaGetSymbolAddress((void**)&px,   g_x);
    cudaGetSymbolAddress((void**)&pqkv, g_qkv);
    __half *ln16, *att16, *mid16;
    cudaGetSymbolAddress((void**)&ln16,  g_ln16);
    cudaGetSymbolAddress((void**)&att16, g_att16);
    cudaGetSymbolAddress((void**)&mid16, g_mid16);
    __half *qwh, *qwl, *pwh, *pwl, *w1h, *w1l, *w2h, *w2l, *hwh, *hwl;
    cudaGetSymbolAddress((void**)&qwh, g_qkvw_h); cudaGetSymbolAddress((void**)&qwl, g_qkvw_l);
    cudaGetSymbolAddress((void**)&pwh, g_projw_h); cudaGetSymbolAddress((void**)&pwl, g_projw_l);
    cudaGetSymbolAddress((void**)&w1h, g_w1_h);   cudaGetSymbolAddress((void**)&w1l, g_w1_l);
    cudaGetSymbolAddress((void**)&w2h, g_w2_h);   cudaGetSymbolAddress((void**)&w2l, g_w2_l);
    cudaGetSymbolAddress((void**)&hwh, g_hw_h);   cudaGetSymbolAddress((void**)&hwl, g_hw_l);

    cudaFuncSetAttribute(tc_gemm<1,0,0,0>, cudaFuncAttributeMaxDynamicSharedMemorySize, 3 * STG);
    cudaFuncSetAttribute(tc_gemm<1,0,1,0>, cudaFuncAttributeMaxDynamicSharedMemorySize, 3 * STG);
    cudaFuncSetAttribute(tc_gemm<1,1,0,1>, cudaFuncAttributeMaxDynamicSharedMemorySize, 3 * STG);
    cudaFuncSetAttribute(tc_gemm<0,0,0,0>, cudaFuncAttributeMaxDynamicSharedMemorySize, 3 * STG);

    // ---- weight conversion (once per replay) ----
    {
        int n;
        n = L_ * C_ * 3 * C_ / 4;
        convert_kernel<<<(n + 255) / 256, 256>>>(qkv_w, qwh, qwl, n);
        n = L_ * C_ * C_ / 4;
        convert_kernel<<<(n + 255) / 256, 256>>>(proj_w, pwh, pwl, n);
        n = L_ * C_ * F_ / 4;
        convert_kernel<<<(n + 255) / 256, 256>>>(w1, w1h, w1l, n);
        n = L_ * F_ * C_ / 4;
        convert_kernel<<<(n + 255) / 256, 256>>>(w2, w2h, w2l, n);
        n = C_ * VP_ / 4;
        convert_head_kernel<<<(n + 255) / 256, 256>>>(head_w, hwh, hwl);
    }

    embed_kernel<<<M_, 256>>>(idx, wte, pte, px);

    for (int l = 0; l < L_; l++) {
        const __half* qwh_l = qwh + (size_t)l * C_ * 3 * C_;
        const __half* qwl_l = qwl + (size_t)l * C_ * 3 * C_;
        const __half* pwh_l = pwh + (size_t)l * C_ * C_;
        const __half* pwl_l = pwl + (size_t)l * C_ * C_;
        const __half* w1h_l = w1h + (size_t)l * C_ * F_;
        const __half* w1l_l = w1l + (size_t)l * C_ * F_;
        const __half* w2h_l = w2h + (size_t)l * F_ * C_;
        const __half* w2l_l = w2l + (size_t)l * F_ * C_;

        layernorm_kernel<<<M_, 256>>>(px, ln1_s + (size_t)l * C_, ln1_b + (size_t)l * C_, ln16);

        // qkv = ln @ qkv_w + qkv_b  -> fp32
        tc_gemm<1,0,0,0><<<dim3(M_ / 128, 3 * C_ / 128), 256, 3 * STG>>>(
            ln16, qwh_l, qwl_l, qkv_b + (size_t)l * 3 * C_, nullptr,
            pqkv, nullptr, M_, 3 * C_, 3 * C_, C_);

        attn_kernel<<<dim3(T_ / 64, B_ * H_), 128>>>(pqkv, att16);

        // x = x + att @ proj_w + proj_b
        tc_gemm<1,0,1,0><<<dim3(M_ / 128, C_ / 128), 256, 3 * STG>>>(
            att16, pwh_l, pwl_l, proj_b + (size_t)l * C_, px,
            px, nullptr, M_, C_, C_, C_);

        layernorm_kernel<<<M_, 256>>>(px, ln2_s + (size_t)l * C_, ln2_b + (size_t)l * C_, ln16);

        // mid = gelu(ln2 @ w1 + b1) -> fp16
        tc_gemm<1,1,0,1><<<dim3(M_ / 128, F_ / 128), 256, 3 * STG>>>(
            ln16, w1h_l, w1l_l, b1 + (size_t)l * F_, nullptr,
            nullptr, mid16, M_, F_, F_, C_);

        // x = x + mid @ w2 + b2
        tc_gemm<1,0,1,0><<<dim3(M_ / 128, C_ / 128), 256, 3 * STG>>>(
            mid16, w2h_l, w2l_l, b2 + (size_t)l * C_, px,
            px, nullptr, M_, C_, C_, F_);
    }

    layernorm_kernel<<<M_, 256>>>(px, lnf_s, lnf_b, ln16);

    // logits = lnf @ head_w   [2048 x 50257], N padded to 50304
    tc_gemm<0,0,0,0><<<dim3(M_ / 128, VP_ / 128), 256, 3 * STG>>>(
        ln16, hwh, hwl, nullptr, nullptr,
        out, nullptr, M_, VP_, V_, C_);
}

// round 9
// speedup vs baseline: 8.2854x; 1.1624x over previous
#include <cuda_runtime.h>
#include <cuda_fp16.h>
#include <math.h>
#include <stdint.h>

// ---------------- problem constants ----------------
#define L_  6
#define B_  2
#define T_  1024
#define C_  768
#define H_  12
#define D_  64
#define F_  3072
#define V_  50257
#define VP_ 50304              // V padded to /128
#define M_  (B_ * T_)          // 2048 rows
#define EPS_ 1e-5f

// ---------------- scratch (device globals, no runtime alloc) ----------------
__device__ float  g_x    [M_ * C_];     // residual stream (fp32)
__device__ __half g_qkv16[M_ * 3 * C_]; // qkv (fp16)

// single-plane fp16 activations
__device__ __half g_ln16 [M_ * C_];
__device__ __half g_att16[M_ * C_];
__device__ __half g_mid16[M_ * F_];

// weight planes (fp16 hi/lo), converted once per replay
__device__ __half g_qkvw_h[L_ * C_ * 3 * C_], g_qkvw_l[L_ * C_ * 3 * C_];
__device__ __half g_projw_h[L_ * C_ * C_],    g_projw_l[L_ * C_ * C_];
__device__ __half g_w1_h  [L_ * C_ * F_],     g_w1_l  [L_ * C_ * F_];
__device__ __half g_w2_h  [L_ * F_ * C_],     g_w2_l  [L_ * F_ * C_];
__device__ __half g_hw_h  [C_ * VP_];          // head: single fp16 plane

// ---------------- helpers ----------------
__device__ __forceinline__ uint32_t smem_u32(const void* p) {
    uint32_t a;
    asm("{ .reg .u64 t; cvta.to.shared.u64 t, %1; cvt.u32.u64 %0, t; }" : "=r"(a) : "l"(p));
    return a;
}
__device__ __forceinline__ void cp16(uint32_t dst, const void* src) {
    asm volatile("cp.async.cg.shared.global [%0], [%1], 16;" :: "r"(dst), "l"(src));
}
__device__ __forceinline__ void cp_commit() {
    asm volatile("cp.async.commit_group;" ::: "memory");
}
__device__ __forceinline__ void ldsm_x4(uint32_t* r, uint32_t a) {
    asm volatile("ldmatrix.sync.aligned.m8n8.x4.shared.b16 {%0,%1,%2,%3}, [%4];"
        : "=r"(r[0]), "=r"(r[1]), "=r"(r[2]), "=r"(r[3]) : "r"(a));
}
__device__ __forceinline__ void ldsm_x2(uint32_t* r, uint32_t a) {
    asm volatile("ldmatrix.sync.aligned.m8n8.x2.shared.b16 {%0,%1}, [%2];"
        : "=r"(r[0]), "=r"(r[1]) : "r"(a));
}
__device__ __forceinline__ void ldsm_x2t(uint32_t* r, uint32_t a) {
    asm volatile("ldmatrix.sync.aligned.m8n8.x2.trans.shared.b16 {%0,%1}, [%2];"
        : "=r"(r[0]), "=r"(r[1]) : "r"(a));
}
__device__ __forceinline__ void mma_f16(float* d, const uint32_t* a, const uint32_t* b) {
    asm volatile("mma.sync.aligned.m16n8k16.row.col.f32.f16.f16.f32 "
        "{%0,%1,%2,%3}, {%4,%5,%6,%7}, {%8,%9}, {%0,%1,%2,%3};"
        : "+f"(d[0]), "+f"(d[1]), "+f"(d[2]), "+f"(d[3])
        : "r"(a[0]), "r"(a[1]), "r"(a[2]), "r"(a[3]), "r"(b[0]), "r"(b[1]));
}
__device__ __forceinline__ uint32_t packh2(float a, float b) {
    __half2 t = __floats2half2_rn(a, b);
    return *(uint32_t*)&t;
}
__device__ __forceinline__ void split1h(float x, __half& h, __half& l) {
    h = __float2half_rn(x);
    l = __float2half_rn(x - __half2float(h));
}
__device__ __forceinline__ float gelu_exact(float v) {
    return 0.5f * v * (1.0f + erff(v * 0.70710678118654752f));
}

// ---------------- weight conversion (fp32 -> fp16 hi/lo) ----------------
__global__ void convert_kernel(const float* __restrict__ src,
                               __half* __restrict__ hi,
                               __half* __restrict__ lo, int n4) {
    int e = blockIdx.x * blockDim.x + threadIdx.x;
    if (e >= n4) return;
    float4 v = *(const float4*)(src + (size_t)e * 4);
    __half h[4], l[4];
    split1h(v.x, h[0], l[0]); split1h(v.y, h[1], l[1]);
    split1h(v.z, h[2], l[2]); split1h(v.w, h[3], l[3]);
    *(__half2*)(hi + (size_t)e * 4)     = *(__half2*)&h[0];
    *(__half2*)(hi + (size_t)e * 4 + 2) = *(__half2*)&h[2];
    *(__half2*)(lo + (size_t)e * 4)     = *(__half2*)&l[0];
    *(__half2*)(lo + (size_t)e * 4 + 2) = *(__half2*)&l[2];
}

// head_w [C_ x V_] -> padded single fp16 plane [C_ x VP_]
__global__ void convert_head_kernel(const float* __restrict__ src,
                                    __half* __restrict__ hi) {
    int e = blockIdx.x * blockDim.x + threadIdx.x;
    if (e >= C_ * (VP_ / 4)) return;
    int row = e / (VP_ / 4);
    int c0  = (e % (VP_ / 4)) * 4;
    __half h[4];
    #pragma unroll
    for (int j = 0; j < 4; j++) {
        int c = c0 + j;
        h[j] = __float2half_rn((c < V_) ? src[(size_t)row * V_ + c] : 0.0f);
    }
    size_t o = (size_t)row * VP_ + c0;
    *(__half2*)(hi + o)     = *(__half2*)&h[0];
    *(__half2*)(hi + o + 2) = *(__half2*)&h[2];
}

// ---------------- embedding ----------------
__global__ void embed_kernel(const int* __restrict__ idx,
                             const float* __restrict__ wte,
                             const float* __restrict__ pte,
                             float* __restrict__ x) {
    int r = blockIdx.x;
    int t = r % T_;
    int tok = idx[r];
    const float* wrow = wte + (size_t)tok * C_;
    const float* prow = pte + (size_t)t * C_;
    float* xr = x + (size_t)r * C_;
    for (int c = threadIdx.x; c < C_; c += blockDim.x)
        xr[c] = wrow[c] + prow[c];
}

// ---------------- layernorm -> single fp16 plane ----------------
__global__ void layernorm_kernel(const float* __restrict__ x,
                                 const float* __restrict__ sc,
                                 const float* __restrict__ bi,
                                 __half* __restrict__ y) {
    __shared__ float sh1[256];
    __shared__ float sh2[256];
    int r = blockIdx.x;
    int tid = threadIdx.x;
    const float* xr = x + (size_t)r * C_;
    float v0 = xr[tid], v1 = xr[tid + 256], v2 = xr[tid + 512];
    float s  = v0 + v1 + v2;
    float ss = v0 * v0 + v1 * v1 + v2 * v2;
    sh1[tid] = s; sh2[tid] = ss;
    __syncthreads();
    for (int off = 128; off > 0; off >>= 1) {
        if (tid < off) { sh1[tid] += sh1[tid + off]; sh2[tid] += sh2[tid + off]; }
        __syncthreads();
    }
    float mu  = sh1[0] * (1.0f / C_);
    float var = sh2[0] * (1.0f / C_) - mu * mu;
    float rstd = rsqrtf(var + EPS_);
    size_t base = (size_t)r * C_;
    #pragma unroll
    for (int q = 0; q < 3; q++) {
        int c = tid + q * 256;
        float v = (q == 0 ? v0 : (q == 1 ? v1 : v2));
        y[base + c] = __float2half_rn((v - mu) * rstd * sc[c] + bi[c]);
    }
}

// ---------------- FA2-style block attention, fp16 qkv, cp.async tiles ----------------
// Grid (T/64, B*H). Block 128 threads (4 warps, each 16 q rows).
__global__ __launch_bounds__(128) void attn_kernel(const __half* __restrict__ qkv,
                                                   __half* __restrict__ o16) {
    __shared__ __align__(1024) __half sQ[64 * 64];
    __shared__ __align__(1024) __half sK[64 * 64];
    __shared__ __align__(1024) __half sV[64 * 64];
    uint32_t qB = smem_u32(sQ), kB = smem_u32(sK), vB = smem_u32(sV);
    int tid = threadIdx.x, lane = tid & 31, wid = tid >> 5;
    int q0 = blockIdx.x * 64;
    int bh = blockIdx.y;
    int b = bh / H_, h = bh % H_;
    const __half* base = qkv + (size_t)b * T_ * 3 * C_ + h * D_;

    // ---- load Q tile (fp16 rows = 128B, pure cp.async, swizzled) ----
    #pragma unroll
    for (int i = 0; i < 4; i++) {
        int e = tid + 128 * i;          // 0..511 16B-units
        int r = e >> 3, u = e & 7;
        uint32_t d = qB + (uint32_t)(r * 128 + ((u ^ (r & 7)) << 4));
        cp16(d, base + (size_t)(q0 + r) * 3 * C_ + u * 8);
    }
    cp_commit();
    asm volatile("cp.async.wait_group 0;" ::: "memory");
    __syncthreads();

    // ---- Q fragments (once) ----
    uint32_t qa[4][4];
    #pragma unroll
    for (int ks = 0; ks < 4; ks++) {
        int r = wid * 16 + (lane & 15);
        int c = ks * 2 + (lane >> 4);
        ldsm_x4(qa[ks], qB + (uint32_t)(r * 128 + ((c ^ (r & 7)) << 4)));
    }

    float m1 = -1e30f, m2 = -1e30f, l1 = 0.0f, l2 = 0.0f;
    float oacc[8][4];
    #pragma unroll
    for (int dt = 0; dt < 8; dt++)
        #pragma unroll
        for (int i = 0; i < 4; i++) oacc[dt][i] = 0.0f;

    int r1loc = wid * 16 + (lane >> 2);

    for (int j0 = 0; j0 <= q0; j0 += 64) {
        __syncthreads();
        // ---- load K,V tiles via cp.async ----
        #pragma unroll
        for (int i = 0; i < 4; i++) {
            int e = tid + 128 * i;
            int r = e >> 3, u = e & 7;
            uint32_t off = (uint32_t)(r * 128 + ((u ^ (r & 7)) << 4));
            cp16(kB + off, base + C_     + (size_t)(j0 + r) * 3 * C_ + u * 8);
            cp16(vB + off, base + 2 * C_ + (size_t)(j0 + r) * 3 * C_ + u * 8);
        }
        cp_commit();
        asm volatile("cp.async.wait_group 0;" ::: "memory");
        __syncthreads();

        // ---- S = Q K^T (scale applied to fragments after) ----
        float sc[8][4];
        #pragma unroll
        for (int nt = 0; nt < 8; nt++)
            #pragma unroll
            for (int i = 0; i < 4; i++) sc[nt][i] = 0.0f;
        #pragma unroll
        for (int ks = 0; ks < 4; ks++) {
            #pragma unroll
            for (int nt = 0; nt < 8; nt++) {
                int n = nt * 8 + (lane & 7);
                int g = ks * 2 + ((lane >> 3) & 1);
                uint32_t kb[2];
                ldsm_x2(kb, kB + (uint32_t)(n * 128 + ((g ^ (n & 7)) << 4)));
                mma_f16(sc[nt], qa[ks], kb);
            }
        }
        #pragma unroll
        for (int nt = 0; nt < 8; nt++)
            #pragma unroll
            for (int i = 0; i < 4; i++) sc[nt][i] *= 0.125f;

        // ---- causal mask on diagonal tile ----
        if (j0 == q0) {
            #pragma unroll
            for (int nt = 0; nt < 8; nt++) {
                int cb = nt * 8 + (lane & 3) * 2;
                if (cb     > r1loc) sc[nt][0] = -1e30f;
                if (cb + 1 > r1loc) sc[nt][1] = -1e30f;
                if (cb     > r1loc + 8) sc[nt][2] = -1e30f;
                if (cb + 1 > r1loc + 8) sc[nt][3] = -1e30f;
            }
        }

        // ---- online softmax ----
        float nm1 = m1, nm2 = m2;
        #pragma unroll
        for (int nt = 0; nt < 8; nt++) {
            nm1 = fmaxf(nm1, fmaxf(sc[nt][0], sc[nt][1]));
            nm2 = fmaxf(nm2, fmaxf(sc[nt][2], sc[nt][3]));
        }
        #pragma unroll
        for (int o = 1; o <= 2; o <<= 1) {
            nm1 = fmaxf(nm1, __shfl_xor_sync(0xffffffff, nm1, o));
            nm2 = fmaxf(nm2, __shfl_xor_sync(0xffffffff, nm2, o));
        }
        float corr1 = __expf(m1 - nm1);
        float corr2 = __expf(m2 - nm2);
        m1 = nm1; m2 = nm2;
        float rs1 = 0.0f, rs2 = 0.0f;
        #pragma unroll
        for (int nt = 0; nt < 8; nt++) {
            sc[nt][0] = __expf(sc[nt][0] - m1);
            sc[nt][1] = __expf(sc[nt][1] - m1);
            sc[nt][2] = __expf(sc[nt][2] - m2);
            sc[nt][3] = __expf(sc[nt][3] - m2);
            rs1 += sc[nt][0] + sc[nt][1];
            rs2 += sc[nt][2] + sc[nt][3];
        }
        #pragma unroll
        for (int o = 1; o <= 2; o <<= 1) {
            rs1 += __shfl_xor_sync(0xffffffff, rs1, o);
            rs2 += __shfl_xor_sync(0xffffffff, rs2, o);
        }
        l1 = l1 * corr1 + rs1;
        l2 = l2 * corr2 + rs2;
        #pragma unroll
        for (int dt = 0; dt < 8; dt++) {
            oacc[dt][0] *= corr1; oacc[dt][1] *= corr1;
            oacc[dt][2] *= corr2; oacc[dt][3] *= corr2;
        }

        // ---- O += P V ----
        #pragma unroll
        for (int ks = 0; ks < 4; ks++) {
            uint32_t pa[4];
            pa[0] = packh2(sc[2 * ks][0],     sc[2 * ks][1]);
            pa[1] = packh2(sc[2 * ks][2],     sc[2 * ks][3]);
            pa[2] = packh2(sc[2 * ks + 1][0], sc[2 * ks + 1][1]);
            pa[3] = packh2(sc[2 * ks + 1][2], sc[2 * ks + 1][3]);
            #pragma unroll
            for (int dt = 0; dt < 8; dt++) {
                int kt = ks * 16 + (lane & 15);
                uint32_t vb[2];
                ldsm_x2t(vb, vB + (uint32_t)(kt * 128 + ((dt ^ (kt & 7)) << 4)));
                mma_f16(oacc[dt], pa, vb);
            }
        }
    }

    // ---- epilogue ----
    float inv1 = 1.0f / l1, inv2 = 1.0f / l2;
    int rowg = b * T_ + q0 + r1loc;
    #pragma unroll
    for (int dt = 0; dt < 8; dt++) {
        int col = h * D_ + dt * 8 + (lane & 3) * 2;
        *(__half2*)(o16 + (size_t)rowg * C_ + col) =
            __floats2half2_rn(oacc[dt][0] * inv1, oacc[dt][1] * inv1);
        *(__half2*)(o16 + (size_t)(rowg + 8) * C_ + col) =
            __floats2half2_rn(oacc[dt][2] * inv2, oacc[dt][3] * inv2);
    }
}

// ================= fp16 GEMM: C = A*(Bh[+Bl]), 3-stage cp.async =================
// Tile 128x128, BK=64, 256 threads.
// TERMS==2 stage (48KB): A @0, Bh @16384, Bl @32768.
// TERMS==1 stage (32KB): A @0, Bh @16384.

template<int HAS_BIAS, int DO_GELU, int DO_RES, int WRITE_F16, int TERMS>
__global__ __launch_bounds__(256, 1) void tc_gemm(
        const __half* __restrict__ Af,
        const __half* __restrict__ Bhi, const __half* __restrict__ Blo,
        const float* __restrict__ bias, const float* __restrict__ res,
        float* __restrict__ Cf, __half* __restrict__ C16,
        int M, int Nb, int Nc, int K) {
    constexpr uint32_t STGB = (TERMS == 2) ? 49152u : 32768u;
    extern __shared__ __align__(1024) char dsm[];
    uint32_t sb = smem_u32(dsm);
    const int tid = threadIdx.x, lane = tid & 31, wid = tid >> 5;
    const int wm = wid >> 2, wn = wid & 3;
    const int m0 = blockIdx.x * 128, n0 = blockIdx.y * 128;
    const int niter = K >> 6;

    float acc[4][4][4];
    #pragma unroll
    for (int a = 0; a < 4; a++)
        #pragma unroll
        for (int b = 0; b < 4; b++)
            #pragma unroll
            for (int c = 0; c < 4; c++) acc[a][b][c] = 0.0f;

    auto PREFETCH = [&](int it) {
        if (it < niter) {
            int k0 = it << 6;
            uint32_t buf = sb + (it % 3) * STGB;
            #pragma unroll
            for (int i = 0; i < 4; i++) {
                int e = tid + 256 * i;
                int r = e >> 3, u = e & 7;
                uint32_t d = buf + (uint32_t)(r * 128 + ((u ^ (r & 7)) << 4));
                cp16(d, Af + (size_t)(m0 + r) * K + k0 + u * 8);
            }
            #pragma unroll
            for (int i = 0; i < 4; i++) {
                int e = tid + 256 * i;
                int kr = e >> 4, u = e & 15;
                uint32_t d = buf + 16384 + (uint32_t)(kr * 256 + ((u ^ (kr & 7)) << 4));
                size_t so = (size_t)(k0 + kr) * Nb + n0 + u * 8;
                cp16(d, Bhi + so);
                if (TERMS == 2) cp16(d + 16384, Blo + so);
            }
        }
        cp_commit();
    };

    auto COMPUTE = [&](int stg) {
        uint32_t aBase = sb + stg * STGB;
        uint32_t bBase = aBase + 16384;
        #pragma unroll
        for (int ks = 0; ks < 4; ks++) {
            uint32_t af[4][4];
            #pragma unroll
            for (int mt = 0; mt < 4; mt++) {
                int r = wm * 64 + mt * 16 + (lane & 15);
                int c = ks * 2 + (lane >> 4);
                uint32_t off = (uint32_t)(r * 128 + ((c ^ (r & 7)) << 4));
                ldsm_x4(af[mt], aBase + off);
            }
            uint32_t bh[4][2], blr[4][2];
            #pragma unroll
            for (int nt = 0; nt < 4; nt++) {
                int kt = ks * 16 + (lane & 15);
                int c = wn * 4 + nt;
                uint32_t off = (uint32_t)(kt * 256 + ((c ^ (kt & 7)) << 4));
                ldsm_x2t(bh[nt],  bBase + off);
                if (TERMS == 2) ldsm_x2t(blr[nt], bBase + 16384 + off);
            }
            #pragma unroll
            for (int mt = 0; mt < 4; mt++)
                #pragma unroll
                for (int nt = 0; nt < 4; nt++) {
                    mma_f16(acc[mt][nt], af[mt], bh[nt]);
                    if (TERMS == 2) mma_f16(acc[mt][nt], af[mt], blr[nt]);
                }
        }
    };

    PREFETCH(0);
    PREFETCH(1);
    for (int it = 0; it < niter; it++) {
        asm volatile("cp.async.wait_group 1;" ::: "memory");
        __syncthreads();
        COMPUTE(it % 3);
        PREFETCH(it + 2);
    }

    // epilogue
    #pragma unroll
    for (int mt = 0; mt < 4; mt++) {
        int r0 = m0 + wm * 64 + mt * 16 + (lane >> 2);
        #pragma unroll
        for (int nt = 0; nt < 4; nt++) {
            int c0 = n0 + wn * 32 + nt * 8 + (lane & 3) * 2;
            float v[4];
            #pragma unroll
            for (int i = 0; i < 4; i++) {
                v[i] = acc[mt][nt][i];
                int col = c0 + (i & 1);
                if (HAS_BIAS && col < Nc) v[i] += bias[col];
                if (DO_GELU) v[i] = gelu_exact(v[i]);
            }
            if (WRITE_F16) {
                #pragma unroll
                for (int half_i = 0; half_i < 2; half_i++) {
                    int row = r0 + half_i * 8;
                    size_t o = (size_t)row * Nc + c0;
                    *(__half2*)(C16 + o) =
                        __floats2half2_rn(v[half_i * 2], v[half_i * 2 + 1]);
                }
            } else {
                #pragma unroll
                for (int i = 0; i < 4; i++) {
                    int row = r0 + (i >> 1) * 8;
                    int col = c0 + (i & 1);
                    if (col < Nc) {
                        float w = v[i];
                        if (DO_RES) w += res[(size_t)row * Nc + col];
                        Cf[(size_t)row * Nc + col] = w;
                    }
                }
            }
        }
    }
}

// ---------------- launch ----------------
extern "C" void kernel_launch(void* const* d_in, const int* in_sizes, int n_in,
                              void* d_out, int out_size) {
    const int*   idx    = (const int*)  d_in[0];
    const float* wte    = (const float*)d_in[1];
    const float* pte    = (const float*)d_in[2];
    const float* ln1_s  = (const float*)d_in[3];
    const float* ln1_b  = (const float*)d_in[4];
    const float* qkv_w  = (const float*)d_in[5];
    const float* qkv_b  = (const float*)d_in[6];
    const float* proj_w = (const float*)d_in[7];
    const float* proj_b = (const float*)d_in[8];
    const float* ln2_s  = (const float*)d_in[9];
    const float* ln2_b  = (const float*)d_in[10];
    const float* w1     = (const float*)d_in[11];
    const float* b1     = (const float*)d_in[12];
    const float* w2     = (const float*)d_in[13];
    const float* b2     = (const float*)d_in[14];
    const float* lnf_s  = (const float*)d_in[15];
    const float* lnf_b  = (const float*)d_in[16];
    const float* head_w = (const float*)d_in[17];
    float* out = (float*)d_out;

    float* px;
    cudaGetSymbolAddress((void**)&px, g_x);
    __half *qkv16, *ln16, *att16, *mid16;
    cudaGetSymbolAddress((void**)&qkv16, g_qkv16);
    cudaGetSymbolAddress((void**)&ln16,  g_ln16);
    cudaGetSymbolAddress((void**)&att16, g_att16);
    cudaGetSymbolAddress((void**)&mid16, g_mid16);
    __half *qwh, *qwl, *pwh, *pwl, *w1h, *w1l, *w2h, *w2l, *hwh;
    cudaGetSymbolAddress((void**)&qwh, g_qkvw_h); cudaGetSymbolAddress((void**)&qwl, g_qkvw_l);
    cudaGetSymbolAddress((void**)&pwh, g_projw_h); cudaGetSymbolAddress((void**)&pwl, g_projw_l);
    cudaGetSymbolAddress((void**)&w1h, g_w1_h);   cudaGetSymbolAddress((void**)&w1l, g_w1_l);
    cudaGetSymbolAddress((void**)&w2h, g_w2_h);   cudaGetSymbolAddress((void**)&w2l, g_w2_l);
    cudaGetSymbolAddress((void**)&hwh, g_hw_h);

    cudaFuncSetAttribute(tc_gemm<1,0,0,1,2>, cudaFuncAttributeMaxDynamicSharedMemorySize, 3 * 49152);
    cudaFuncSetAttribute(tc_gemm<1,0,1,0,2>, cudaFuncAttributeMaxDynamicSharedMemorySize, 3 * 49152);
    cudaFuncSetAttribute(tc_gemm<1,1,0,1,2>, cudaFuncAttributeMaxDynamicSharedMemorySize, 3 * 49152);
    cudaFuncSetAttribute(tc_gemm<0,0,0,0,1>, cudaFuncAttributeMaxDynamicSharedMemorySize, 3 * 32768);

    // ---- weight conversion (once per replay) ----
    {
        int n;
        n = L_ * C_ * 3 * C_ / 4;
        convert_kernel<<<(n + 255) / 256, 256>>>(qkv_w, qwh, qwl, n);
        n = L_ * C_ * C_ / 4;
        convert_kernel<<<(n + 255) / 256, 256>>>(proj_w, pwh, pwl, n);
        n = L_ * C_ * F_ / 4;
        convert_kernel<<<(n + 255) / 256, 256>>>(w1, w1h, w1l, n);
        n = L_ * F_ * C_ / 4;
        convert_kernel<<<(n + 255) / 256, 256>>>(w2, w2h, w2l, n);
        n = C_ * VP_ / 4;
        convert_head_kernel<<<(n + 255) / 256, 256>>>(head_w, hwh);
    }

    embed_kernel<<<M_, 256>>>(idx, wte, pte, px);

    for (int l = 0; l < L_; l++) {
        const __half* qwh_l = qwh + (size_t)l * C_ * 3 * C_;
        const __half* qwl_l = qwl + (size_t)l * C_ * 3 * C_;
        const __half* pwh_l = pwh + (size_t)l * C_ * C_;
        const __half* pwl_l = pwl + (size_t)l * C_ * C_;
        const __half* w1h_l = w1h + (size_t)l * C_ * F_;
        const __half* w1l_l = w1l + (size_t)l * C_ * F_;
        const __half* w2h_l = w2h + (size_t)l * F_ * C_;
        const __half* w2l_l = w2l + (size_t)l * F_ * C_;

        layernorm_kernel<<<M_, 256>>>(px, ln1_s + (size_t)l * C_, ln1_b + (size_t)l * C_, ln16);

        // qkv = ln @ qkv_w + qkv_b  -> fp16
        tc_gemm<1,0,0,1,2><<<dim3(M_ / 128, 3 * C_ / 128), 256, 3 * 49152>>>(
            ln16, qwh_l, qwl_l, qkv_b + (size_t)l * 3 * C_, nullptr,
            nullptr, qkv16, M_, 3 * C_, 3 * C_, C_);

        attn_kernel<<<dim3(T_ / 64, B_ * H_), 128>>>(qkv16, att16);

        // x = x + att @ proj_w + proj_b
        tc_gemm<1,0,1,0,2><<<dim3(M_ / 128, C_ / 128), 256, 3 * 49152>>>(
            att16, pwh_l, pwl_l, proj_b + (size_t)l * C_, px,
            px, nullptr, M_, C_, C_, C_);

        layernorm_kernel<<<M_, 256>>>(px, ln2_s + (size_t)l * C_, ln2_b + (size_t)l * C_, ln16);

        // mid = gelu(ln2 @ w1 + b1) -> fp16
        tc_gemm<1,1,0,1,2><<<dim3(M_ / 128, F_ / 128), 256, 3 * 49152>>>(
            ln16, w1h_l, w1l_l, b1 + (size_t)l * F_, nullptr,
            nullptr, mid16, M_, F_, F_, C_);

        // x = x + mid @ w2 + b2
        tc_gemm<1,0,1,0,2><<<dim3(M_ / 128, C_ / 128), 256, 3 * 49152>>>(
            mid16, w2h_l, w2l_l, b2 + (size_t)l * C_, px,
            px, nullptr, M_, C_, C_, F_);
    }

    layernorm_kernel<<<M_, 256>>>(px, lnf_s, lnf_b, ln16);

    // logits = lnf @ head_w, single fp16 term, N padded to 50304
    tc_gemm<0,0,0,0,1><<<dim3(M_ / 128, VP_ / 128), 256, 3 * 32768>>>(
        ln16, hwh, nullptr, nullptr, nullptr,
        out, nullptr, M_, VP_, V_, C_);
}

// round 10
// speedup vs baseline: 9.1506x; 1.1044x over previous
#include <cuda_runtime.h>
#include <cuda_fp16.h>
#include <math.h>
#include <stdint.h>

// ---------------- problem constants ----------------
#define L_  6
#define B_  2
#define T_  1024
#define C_  768
#define H_  12
#define D_  64
#define F_  3072
#define V_  50257
#define VP_ 50304              // V padded to /128
#define M_  (B_ * T_)          // 2048 rows
#define EPS_ 1e-5f

// ---------------- scratch (device globals, no runtime alloc) ----------------
__device__ float  g_x    [M_ * C_];     // residual stream (fp32)
__device__ __half g_qkv16[M_ * 3 * C_]; // qkv (fp16)

// single-plane fp16 activations
__device__ __half g_ln16 [M_ * C_];
__device__ __half g_att16[M_ * C_];
__device__ __half g_mid16[M_ * F_];

// weight planes, converted once per replay
__device__ __half g_qkvw_h[L_ * C_ * 3 * C_];                       // 1-term
__device__ __half g_projw_h[L_ * C_ * C_], g_projw_l[L_ * C_ * C_]; // 2-term
__device__ __half g_w1_h  [L_ * C_ * F_];                           // 1-term
__device__ __half g_w2_h  [L_ * F_ * C_], g_w2_l  [L_ * F_ * C_];   // 2-term
__device__ __half g_hw_h  [C_ * VP_];                               // 1-term

// ---------------- helpers ----------------
__device__ __forceinline__ uint32_t smem_u32(const void* p) {
    uint32_t a;
    asm("{ .reg .u64 t; cvta.to.shared.u64 t, %1; cvt.u32.u64 %0, t; }" : "=r"(a) : "l"(p));
    return a;
}
__device__ __forceinline__ void cp16(uint32_t dst, const void* src) {
    asm volatile("cp.async.cg.shared.global [%0], [%1], 16;" :: "r"(dst), "l"(src));
}
__device__ __forceinline__ void cp_commit() {
    asm volatile("cp.async.commit_group;" ::: "memory");
}
__device__ __forceinline__ void ldsm_x4(uint32_t* r, uint32_t a) {
    asm volatile("ldmatrix.sync.aligned.m8n8.x4.shared.b16 {%0,%1,%2,%3}, [%4];"
        : "=r"(r[0]), "=r"(r[1]), "=r"(r[2]), "=r"(r[3]) : "r"(a));
}
__device__ __forceinline__ void ldsm_x2(uint32_t* r, uint32_t a) {
    asm volatile("ldmatrix.sync.aligned.m8n8.x2.shared.b16 {%0,%1}, [%2];"
        : "=r"(r[0]), "=r"(r[1]) : "r"(a));
}
__device__ __forceinline__ void ldsm_x2t(uint32_t* r, uint32_t a) {
    asm volatile("ldmatrix.sync.aligned.m8n8.x2.trans.shared.b16 {%0,%1}, [%2];"
        : "=r"(r[0]), "=r"(r[1]) : "r"(a));
}
__device__ __forceinline__ void mma_f16(float* d, const uint32_t* a, const uint32_t* b) {
    asm volatile("mma.sync.aligned.m16n8k16.row.col.f32.f16.f16.f32 "
        "{%0,%1,%2,%3}, {%4,%5,%6,%7}, {%8,%9}, {%0,%1,%2,%3};"
        : "+f"(d[0]), "+f"(d[1]), "+f"(d[2]), "+f"(d[3])
        : "r"(a[0]), "r"(a[1]), "r"(a[2]), "r"(a[3]), "r"(b[0]), "r"(b[1]));
}
__device__ __forceinline__ uint32_t packh2(float a, float b) {
    __half2 t = __floats2half2_rn(a, b);
    return *(uint32_t*)&t;
}
__device__ __forceinline__ void split1h(float x, __half& h, __half& l) {
    h = __float2half_rn(x);
    l = __float2half_rn(x - __half2float(h));
}
__device__ __forceinline__ float gelu_exact(float v) {
    return 0.5f * v * (1.0f + erff(v * 0.70710678118654752f));
}

// ---------------- weight conversion ----------------
__global__ void convert_kernel(const float* __restrict__ src,
                               __half* __restrict__ hi,
                               __half* __restrict__ lo, int n4) {
    int e = blockIdx.x * blockDim.x + threadIdx.x;
    if (e >= n4) return;
    float4 v = *(const float4*)(src + (size_t)e * 4);
    __half h[4], l[4];
    split1h(v.x, h[0], l[0]); split1h(v.y, h[1], l[1]);
    split1h(v.z, h[2], l[2]); split1h(v.w, h[3], l[3]);
    *(__half2*)(hi + (size_t)e * 4)     = *(__half2*)&h[0];
    *(__half2*)(hi + (size_t)e * 4 + 2) = *(__half2*)&h[2];
    *(__half2*)(lo + (size_t)e * 4)     = *(__half2*)&l[0];
    *(__half2*)(lo + (size_t)e * 4 + 2) = *(__half2*)&l[2];
}

__global__ void convert_hi_kernel(const float* __restrict__ src,
                                  __half* __restrict__ hi, int n4) {
    int e = blockIdx.x * blockDim.x + threadIdx.x;
    if (e >= n4) return;
    float4 v = *(const float4*)(src + (size_t)e * 4);
    __half h[4];
    h[0] = __float2half_rn(v.x); h[1] = __float2half_rn(v.y);
    h[2] = __float2half_rn(v.z); h[3] = __float2half_rn(v.w);
    *(__half2*)(hi + (size_t)e * 4)     = *(__half2*)&h[0];
    *(__half2*)(hi + (size_t)e * 4 + 2) = *(__half2*)&h[2];
}

// head_w [C_ x V_] -> padded single fp16 plane [C_ x VP_]
__global__ void convert_head_kernel(const float* __restrict__ src,
                                    __half* __restrict__ hi) {
    int e = blockIdx.x * blockDim.x + threadIdx.x;
    if (e >= C_ * (VP_ / 4)) return;
    int row = e / (VP_ / 4);
    int c0  = (e % (VP_ / 4)) * 4;
    __half h[4];
    #pragma unroll
    for (int j = 0; j < 4; j++) {
        int c = c0 + j;
        h[j] = __float2half_rn((c < V_) ? src[(size_t)row * V_ + c] : 0.0f);
    }
    size_t o = (size_t)row * VP_ + c0;
    *(__half2*)(hi + o)     = *(__half2*)&h[0];
    *(__half2*)(hi + o + 2) = *(__half2*)&h[2];
}

// ---------------- embedding ----------------
__global__ void embed_kernel(const int* __restrict__ idx,
                             const float* __restrict__ wte,
                             const float* __restrict__ pte,
                             float* __restrict__ x) {
    int r = blockIdx.x;
    int t = r % T_;
    int tok = idx[r];
    const float* wrow = wte + (size_t)tok * C_;
    const float* prow = pte + (size_t)t * C_;
    float* xr = x + (size_t)r * C_;
    for (int c = threadIdx.x; c < C_; c += blockDim.x)
        xr[c] = wrow[c] + prow[c];
}

// ---------------- layernorm -> single fp16 plane ----------------
__global__ void layernorm_kernel(const float* __restrict__ x,
                                 const float* __restrict__ sc,
                                 const float* __restrict__ bi,
                                 __half* __restrict__ y) {
    __shared__ float sh1[256];
    __shared__ float sh2[256];
    int r = blockIdx.x;
    int tid = threadIdx.x;
    const float* xr = x + (size_t)r * C_;
    float v0 = xr[tid], v1 = xr[tid + 256], v2 = xr[tid + 512];
    float s  = v0 + v1 + v2;
    float ss = v0 * v0 + v1 * v1 + v2 * v2;
    sh1[tid] = s; sh2[tid] = ss;
    __syncthreads();
    for (int off = 128; off > 0; off >>= 1) {
        if (tid < off) { sh1[tid] += sh1[tid + off]; sh2[tid] += sh2[tid + off]; }
        __syncthreads();
    }
    float mu  = sh1[0] * (1.0f / C_);
    float var = sh2[0] * (1.0f / C_) - mu * mu;
    float rstd = rsqrtf(var + EPS_);
    size_t base = (size_t)r * C_;
    #pragma unroll
    for (int q = 0; q < 3; q++) {
        int c = tid + q * 256;
        float v = (q == 0 ? v0 : (q == 1 ? v1 : v2));
        y[base + c] = __float2half_rn((v - mu) * rstd * sc[c] + bi[c]);
    }
}

// ---------------- FA2-style block attention, fp16 qkv, cp.async tiles ----------------
__global__ __launch_bounds__(128) void attn_kernel(const __half* __restrict__ qkv,
                                                   __half* __restrict__ o16) {
    __shared__ __align__(1024) __half sQ[64 * 64];
    __shared__ __align__(1024) __half sK[64 * 64];
    __shared__ __align__(1024) __half sV[64 * 64];
    uint32_t qB = smem_u32(sQ), kB = smem_u32(sK), vB = smem_u32(sV);
    int tid = threadIdx.x, lane = tid & 31, wid = tid >> 5;
    int q0 = blockIdx.x * 64;
    int bh = blockIdx.y;
    int b = bh / H_, h = bh % H_;
    const __half* base = qkv + (size_t)b * T_ * 3 * C_ + h * D_;

    #pragma unroll
    for (int i = 0; i < 4; i++) {
        int e = tid + 128 * i;
        int r = e >> 3, u = e & 7;
        uint32_t d = qB + (uint32_t)(r * 128 + ((u ^ (r & 7)) << 4));
        cp16(d, base + (size_t)(q0 + r) * 3 * C_ + u * 8);
    }
    cp_commit();
    asm volatile("cp.async.wait_group 0;" ::: "memory");
    __syncthreads();

    uint32_t qa[4][4];
    #pragma unroll
    for (int ks = 0; ks < 4; ks++) {
        int r = wid * 16 + (lane & 15);
        int c = ks * 2 + (lane >> 4);
        ldsm_x4(qa[ks], qB + (uint32_t)(r * 128 + ((c ^ (r & 7)) << 4)));
    }

    float m1 = -1e30f, m2 = -1e30f, l1 = 0.0f, l2 = 0.0f;
    float oacc[8][4];
    #pragma unroll
    for (int dt = 0; dt < 8; dt++)
        #pragma unroll
        for (int i = 0; i < 4; i++) oacc[dt][i] = 0.0f;

    int r1loc = wid * 16 + (lane >> 2);

    for (int j0 = 0; j0 <= q0; j0 += 64) {
        __syncthreads();
        #pragma unroll
        for (int i = 0; i < 4; i++) {
            int e = tid + 128 * i;
            int r = e >> 3, u = e & 7;
            uint32_t off = (uint32_t)(r * 128 + ((u ^ (r & 7)) << 4));
            cp16(kB + off, base + C_     + (size_t)(j0 + r) * 3 * C_ + u * 8);
            cp16(vB + off, base + 2 * C_ + (size_t)(j0 + r) * 3 * C_ + u * 8);
        }
        cp_commit();
        asm volatile("cp.async.wait_group 0;" ::: "memory");
        __syncthreads();

        float sc[8][4];
        #pragma unroll
        for (int nt = 0; nt < 8; nt++)
            #pragma unroll
            for (int i = 0; i < 4; i++) sc[nt][i] = 0.0f;
        #pragma unroll
        for (int ks = 0; ks < 4; ks++) {
            #pragma unroll
            for (int nt = 0; nt < 8; nt++) {
                int n = nt * 8 + (lane & 7);
                int g = ks * 2 + ((lane >> 3) & 1);
                uint32_t kb[2];
                ldsm_x2(kb, kB + (uint32_t)(n * 128 + ((g ^ (n & 7)) << 4)));
                mma_f16(sc[nt], qa[ks], kb);
            }
        }
        #pragma unroll
        for (int nt = 0; nt < 8; nt++)
            #pragma unroll
            for (int i = 0; i < 4; i++) sc[nt][i] *= 0.125f;

        if (j0 == q0) {
            #pragma unroll
            for (int nt = 0; nt < 8; nt++) {
                int cb = nt * 8 + (lane & 3) * 2;
                if (cb     > r1loc) sc[nt][0] = -1e30f;
                if (cb + 1 > r1loc) sc[nt][1] = -1e30f;
                if (cb     > r1loc + 8) sc[nt][2] = -1e30f;
                if (cb + 1 > r1loc + 8) sc[nt][3] = -1e30f;
            }
        }

        float nm1 = m1, nm2 = m2;
        #pragma unroll
        for (int nt = 0; nt < 8; nt++) {
            nm1 = fmaxf(nm1, fmaxf(sc[nt][0], sc[nt][1]));
            nm2 = fmaxf(nm2, fmaxf(sc[nt][2], sc[nt][3]));
        }
        #pragma unroll
        for (int o = 1; o <= 2; o <<= 1) {
            nm1 = fmaxf(nm1, __shfl_xor_sync(0xffffffff, nm1, o));
            nm2 = fmaxf(nm2, __shfl_xor_sync(0xffffffff, nm2, o));
        }
        float corr1 = __expf(m1 - nm1);
        float corr2 = __expf(m2 - nm2);
        m1 = nm1; m2 = nm2;
        float rs1 = 0.0f, rs2 = 0.0f;
        #pragma unroll
        for (int nt = 0; nt < 8; nt++) {
            sc[nt][0] = __expf(sc[nt][0] - m1);
            sc[nt][1] = __expf(sc[nt][1] - m1);
            sc[nt][2] = __expf(sc[nt][2] - m2);
            sc[nt][3] = __expf(sc[nt][3] - m2);
            rs1 += sc[nt][0] + sc[nt][1];
            rs2 += sc[nt][2] + sc[nt][3];
        }
        #pragma unroll
        for (int o = 1; o <= 2; o <<= 1) {
            rs1 += __shfl_xor_sync(0xffffffff, rs1, o);
            rs2 += __shfl_xor_sync(0xffffffff, rs2, o);
        }
        l1 = l1 * corr1 + rs1;
        l2 = l2 * corr2 + rs2;
        #pragma unroll
        for (int dt = 0; dt < 8; dt++) {
            oacc[dt][0] *= corr1; oacc[dt][1] *= corr1;
            oacc[dt][2] *= corr2; oacc[dt][3] *= corr2;
        }

        #pragma unroll
        for (int ks = 0; ks < 4; ks++) {
            uint32_t pa[4];
            pa[0] = packh2(sc[2 * ks][0],     sc[2 * ks][1]);
            pa[1] = packh2(sc[2 * ks][2],     sc[2 * ks][3]);
            pa[2] = packh2(sc[2 * ks + 1][0], sc[2 * ks + 1][1]);
            pa[3] = packh2(sc[2 * ks + 1][2], sc[2 * ks + 1][3]);
            #pragma unroll
            for (int dt = 0; dt < 8; dt++) {
                int kt = ks * 16 + (lane & 15);
                uint32_t vb[2];
                ldsm_x2t(vb, vB + (uint32_t)(kt * 128 + ((dt ^ (kt & 7)) << 4)));
                mma_f16(oacc[dt], pa, vb);
            }
        }
    }

    float inv1 = 1.0f / l1, inv2 = 1.0f / l2;
    int rowg = b * T_ + q0 + r1loc;
    #pragma unroll
    for (int dt = 0; dt < 8; dt++) {
        int col = h * D_ + dt * 8 + (lane & 3) * 2;
        *(__half2*)(o16 + (size_t)rowg * C_ + col) =
            __floats2half2_rn(oacc[dt][0] * inv1, oacc[dt][1] * inv1);
        *(__half2*)(o16 + (size_t)(rowg + 8) * C_ + col) =
            __floats2half2_rn(oacc[dt][2] * inv2, oacc[dt][3] * inv2);
    }
}

// ================= fp16 GEMM: C = A*(Bh[+Bl]), 3-stage cp.async =================
template<int HAS_BIAS, int DO_GELU, int DO_RES, int WRITE_F16, int TERMS>
__global__ __launch_bounds__(256, 1) void tc_gemm(
        const __half* __restrict__ Af,
        const __half* __restrict__ Bhi, const __half* __restrict__ Blo,
        const float* __restrict__ bias, const float* __restrict__ res,
        float* __restrict__ Cf, __half* __restrict__ C16,
        int M, int Nb, int Nc, int K) {
    constexpr uint32_t STGB = (TERMS == 2) ? 49152u : 32768u;
    extern __shared__ __align__(1024) char dsm[];
    uint32_t sb = smem_u32(dsm);
    const int tid = threadIdx.x, lane = tid & 31, wid = tid >> 5;
    const int wm = wid >> 2, wn = wid & 3;
    const int m0 = blockIdx.x * 128, n0 = blockIdx.y * 128;
    const int niter = K >> 6;

    float acc[4][4][4];
    #pragma unroll
    for (int a = 0; a < 4; a++)
        #pragma unroll
        for (int b = 0; b < 4; b++)
            #pragma unroll
            for (int c = 0; c < 4; c++) acc[a][b][c] = 0.0f;

    auto PREFETCH = [&](int it) {
        if (it < niter) {
            int k0 = it << 6;
            uint32_t buf = sb + (it % 3) * STGB;
            #pragma unroll
            for (int i = 0; i < 4; i++) {
                int e = tid + 256 * i;
                int r = e >> 3, u = e & 7;
                uint32_t d = buf + (uint32_t)(r * 128 + ((u ^ (r & 7)) << 4));
                cp16(d, Af + (size_t)(m0 + r) * K + k0 + u * 8);
            }
            #pragma unroll
            for (int i = 0; i < 4; i++) {
                int e = tid + 256 * i;
                int kr = e >> 4, u = e & 15;
                uint32_t d = buf + 16384 + (uint32_t)(kr * 256 + ((u ^ (kr & 7)) << 4));
                size_t so = (size_t)(k0 + kr) * Nb + n0 + u * 8;
                cp16(d, Bhi + so);
                if (TERMS == 2) cp16(d + 16384, Blo + so);
            }
        }
        cp_commit();
    };

    auto COMPUTE = [&](int stg) {
        uint32_t aBase = sb + stg * STGB;
        uint32_t bBase = aBase + 16384;
        #pragma unroll
        for (int ks = 0; ks < 4; ks++) {
            uint32_t af[4][4];
            #pragma unroll
            for (int mt = 0; mt < 4; mt++) {
                int r = wm * 64 + mt * 16 + (lane & 15);
                int c = ks * 2 + (lane >> 4);
                uint32_t off = (uint32_t)(r * 128 + ((c ^ (r & 7)) << 4));
                ldsm_x4(af[mt], aBase + off);
            }
            uint32_t bh[4][2], blr[4][2];
            #pragma unroll
            for (int nt = 0; nt < 4; nt++) {
                int kt = ks * 16 + (lane & 15);
                int c = wn * 4 + nt;
                uint32_t off = (uint32_t)(kt * 256 + ((c ^ (kt & 7)) << 4));
                ldsm_x2t(bh[nt],  bBase + off);
                if (TERMS == 2) ldsm_x2t(blr[nt], bBase + 16384 + off);
            }
            #pragma unroll
            for (int mt = 0; mt < 4; mt++)
                #pragma unroll
                for (int nt = 0; nt < 4; nt++) {
                    mma_f16(acc[mt][nt], af[mt], bh[nt]);
                    if (TERMS == 2) mma_f16(acc[mt][nt], af[mt], blr[nt]);
                }
        }
    };

    PREFETCH(0);
    PREFETCH(1);
    for (int it = 0; it < niter; it++) {
        asm volatile("cp.async.wait_group 1;" ::: "memory");
        __syncthreads();
        COMPUTE(it % 3);
        PREFETCH(it + 2);
    }

    #pragma unroll
    for (int mt = 0; mt < 4; mt++) {
        int r0 = m0 + wm * 64 + mt * 16 + (lane >> 2);
        #pragma unroll
        for (int nt = 0; nt < 4; nt++) {
            int c0 = n0 + wn * 32 + nt * 8 + (lane & 3) * 2;
            float v[4];
            #pragma unroll
            for (int i = 0; i < 4; i++) {
                v[i] = acc[mt][nt][i];
                int col = c0 + (i & 1);
                if (HAS_BIAS && col < Nc) v[i] += bias[col];
                if (DO_GELU) v[i] = gelu_exact(v[i]);
            }
            if (WRITE_F16) {
                #pragma unroll
                for (int half_i = 0; half_i < 2; half_i++) {
                    int row = r0 + half_i * 8;
                    size_t o = (size_t)row * Nc + c0;
                    *(__half2*)(C16 + o) =
                        __floats2half2_rn(v[half_i * 2], v[half_i * 2 + 1]);
                }
            } else {
                #pragma unroll
                for (int i = 0; i < 4; i++) {
                    int row = r0 + (i >> 1) * 8;
                    int col = c0 + (i & 1);
                    if (col < Nc) {
                        float w = v[i];
                        if (DO_RES) w += res[(size_t)row * Nc + col];
                        Cf[(size_t)row * Nc + col] = w;
                    }
                }
            }
        }
    }
}

// ---------------- launch ----------------
extern "C" void kernel_launch(void* const* d_in, const int* in_sizes, int n_in,
                              void* d_out, int out_size) {
    const int*   idx    = (const int*)  d_in[0];
    const float* wte    = (const float*)d_in[1];
    const float* pte    = (const float*)d_in[2];
    const float* ln1_s  = (const float*)d_in[3];
    const float* ln1_b  = (const float*)d_in[4];
    const float* qkv_w  = (const float*)d_in[5];
    const float* qkv_b  = (const float*)d_in[6];
    const float* proj_w = (const float*)d_in[7];
    const float* proj_b = (const float*)d_in[8];
    const float* ln2_s  = (const float*)d_in[9];
    const float* ln2_b  = (const float*)d_in[10];
    const float* w1     = (const float*)d_in[11];
    const float* b1     = (const float*)d_in[12];
    const float* w2     = (const float*)d_in[13];
    const float* b2     = (const float*)d_in[14];
    const float* lnf_s  = (const float*)d_in[15];
    const float* lnf_b  = (const float*)d_in[16];
    const float* head_w = (const float*)d_in[17];
    float* out = (float*)d_out;

    float* px;
    cudaGetSymbolAddress((void**)&px, g_x);
    __half *qkv16, *ln16, *att16, *mid16;
    cudaGetSymbolAddress((void**)&qkv16, g_qkv16);
    cudaGetSymbolAddress((void**)&ln16,  g_ln16);
    cudaGetSymbolAddress((void**)&att16, g_att16);
    cudaGetSymbolAddress((void**)&mid16, g_mid16);
    __half *qwh, *pwh, *pwl, *w1h, *w2h, *w2l, *hwh;
    cudaGetSymbolAddress((void**)&qwh, g_qkvw_h);
    cudaGetSymbolAddress((void**)&pwh, g_projw_h); cudaGetSymbolAddress((void**)&pwl, g_projw_l);
    cudaGetSymbolAddress((void**)&w1h, g_w1_h);
    cudaGetSymbolAddress((void**)&w2h, g_w2_h);   cudaGetSymbolAddress((void**)&w2l, g_w2_l);
    cudaGetSymbolAddress((void**)&hwh, g_hw_h);

    cudaFuncSetAttribute(tc_gemm<1,0,0,1,1>, cudaFuncAttributeMaxDynamicSharedMemorySize, 3 * 32768);
    cudaFuncSetAttribute(tc_gemm<1,0,1,0,2>, cudaFuncAttributeMaxDynamicSharedMemorySize, 3 * 49152);
    cudaFuncSetAttribute(tc_gemm<1,1,0,1,1>, cudaFuncAttributeMaxDynamicSharedMemorySize, 3 * 32768);
    cudaFuncSetAttribute(tc_gemm<0,0,0,0,1>, cudaFuncAttributeMaxDynamicSharedMemorySize, 3 * 32768);

    // ---- weight conversion (once per replay) ----
    {
        int n;
        n = L_ * C_ * 3 * C_ / 4;
        convert_hi_kernel<<<(n + 255) / 256, 256>>>(qkv_w, qwh, n);
        n = L_ * C_ * C_ / 4;
        convert_kernel<<<(n + 255) / 256, 256>>>(proj_w, pwh, pwl, n);
        n = L_ * C_ * F_ / 4;
        convert_hi_kernel<<<(n + 255) / 256, 256>>>(w1, w1h, n);
        n = L_ * F_ * C_ / 4;
        convert_kernel<<<(n + 255) / 256, 256>>>(w2, w2h, w2l, n);
        n = C_ * VP_ / 4;
        convert_head_kernel<<<(n + 255) / 256, 256>>>(head_w, hwh);
    }

    embed_kernel<<<M_, 256>>>(idx, wte, pte, px);

    for (int l = 0; l < L_; l++) {
        const __half* qwh_l = qwh + (size_t)l * C_ * 3 * C_;
        const __half* pwh_l = pwh + (size_t)l * C_ * C_;
        const __half* pwl_l = pwl + (size_t)l * C_ * C_;
        const __half* w1h_l = w1h + (size_t)l * C_ * F_;
        const __half* w2h_l = w2h + (size_t)l * F_ * C_;
        const __half* w2l_l = w2l + (size_t)l * F_ * C_;

        layernorm_kernel<<<M_, 256>>>(px, ln1_s + (size_t)l * C_, ln1_b + (size_t)l * C_, ln16);

        // qkv = ln @ qkv_w + qkv_b  -> fp16, 1-term (softmax-shielded)
        tc_gemm<1,0,0,1,1><<<dim3(M_ / 128, 3 * C_ / 128), 256, 3 * 32768>>>(
            ln16, qwh_l, nullptr, qkv_b + (size_t)l * 3 * C_, nullptr,
            nullptr, qkv16, M_, 3 * C_, 3 * C_, C_);

        attn_kernel<<<dim3(T_ / 64, B_ * H_), 128>>>(qkv16, att16);

        // x = x + att @ proj_w + proj_b   (2-term: residual writer)
        tc_gemm<1,0,1,0,2><<<dim3(M_ / 128, C_ / 128), 256, 3 * 49152>>>(
            att16, pwh_l, pwl_l, proj_b + (size_t)l * C_, px,
            px, nullptr, M_, C_, C_, C_);

        layernorm_kernel<<<M_, 256>>>(px, ln2_s + (size_t)l * C_, ln2_b + (size_t)l * C_, ln16);

        // mid = gelu(ln2 @ w1 + b1) -> fp16, 1-term (GELU-shielded)
        tc_gemm<1,1,0,1,1><<<dim3(M_ / 128, F_ / 128), 256, 3 * 32768>>>(
            ln16, w1h_l, nullptr, b1 + (size_t)l * F_, nullptr,
            nullptr, mid16, M_, F_, F_, C_);

        // x = x + mid @ w2 + b2   (2-term: residual writer)
        tc_gemm<1,0,1,0,2><<<dim3(M_ / 128, C_ / 128), 256, 3 * 49152>>>(
            mid16, w2h_l, w2l_l, b2 + (size_t)l * C_, px,
            px, nullptr, M_, C_, C_, F_);
    }

    layernorm_kernel<<<M_, 256>>>(px, lnf_s, lnf_b, ln16);

    // logits = lnf @ head_w, single fp16 term, N padded to 50304
    tc_gemm<0,0,0,0,1><<<dim3(M_ / 128, VP_ / 128), 256, 3 * 32768>>>(
        ln16, hwh, nullptr, nullptr, nullptr,
        out, nullptr, M_, VP_, V_, C_);
}